// round 2
// baseline (speedup 1.0000x reference)
#include <cuda_runtime.h>
#include <math.h>

#define BB 32
#define TT 1024
#define JJ 256
#define DD 512
#define DOUT 2048

// Scratch (device globals; no runtime allocation allowed)
__device__ float g_S[BB * TT * JJ];      // 33.5 MB: S then consumed as logits
__device__ float g_a[BB * TT];           // context @ w1
__device__ float g_c[BB * JJ];           // query @ w2
__device__ float g_colmax[BB * JJ];      // max over t per (b,j)
__device__ float g_cinv[BB * JJ];        // 1 / sum_t exp(S - colmax)
__device__ float g_rowmax[BB * TT];      // max over j per (b,t)
__device__ float g_h[BB * DD];           // h = sum_t softmax(rowmax) * ctx

// ---------------------------------------------------------------------------
// K1: a[b,t] = ctx[b,t,:]·w1 ; c[b,j] = qry[b,j,:]·w2   (one warp per row)
// ---------------------------------------------------------------------------
__global__ void bias_kernel(const float* __restrict__ ctx,
                            const float* __restrict__ qry,
                            const float* __restrict__ w) {
    int gwarp = (blockIdx.x * blockDim.x + threadIdx.x) >> 5;
    int lane = threadIdx.x & 31;
    const int nctx = BB * TT;
    const float* row;
    const float* wv;
    float* outp;
    if (gwarp < nctx) {
        row = ctx + (size_t)gwarp * DD;
        wv = w;
        outp = g_a + gwarp;
    } else {
        int r = gwarp - nctx;
        if (r >= BB * JJ) return;
        row = qry + (size_t)r * DD;
        wv = w + DD;
        outp = g_c + r;
    }
    float s = 0.f;
#pragma unroll
    for (int k = lane * 4; k < DD; k += 128) {
        float4 x = *(const float4*)(row + k);
        float4 ww = *(const float4*)(wv + k);
        s += x.x * ww.x + x.y * ww.y + x.z * ww.z + x.w * ww.w;
    }
#pragma unroll
    for (int o = 16; o; o >>= 1) s += __shfl_xor_sync(0xffffffffu, s, o);
    if (lane == 0) *outp = s;
}

// ---------------------------------------------------------------------------
// K2: S[b] = (ctx[b] * w3) @ qry[b]^T + a[b,:,None] + c[b,None,:]
// 128x128 tile, BK=16, 256 threads, 8x8 register tile
// ---------------------------------------------------------------------------
#define BM 128
#define BN 128
#define BK 16
#define TM 8
#define TN 8
#define PAD 4

__global__ __launch_bounds__(256, 2) void gemm1_kernel(
    const float* __restrict__ ctx, const float* __restrict__ qry,
    const float* __restrict__ w) {
    __shared__ float As[BK][BM + PAD];
    __shared__ float Bs[BK][BN + PAD];
    __shared__ float w3s[DD];

    int b = blockIdx.z;
    int m0 = blockIdx.y * BM;
    int n0 = blockIdx.x * BN;
    int tid = threadIdx.x;

    for (int i = tid; i < DD; i += 256) w3s[i] = w[2 * DD + i];
    __syncthreads();

    const float* A = ctx + ((size_t)b * TT + m0) * DD;  // [m][k], ld=DD
    const float* Bq = qry + ((size_t)b * JJ + n0) * DD; // [n][k], ld=DD

    float acc[TM][TN];
#pragma unroll
    for (int i = 0; i < TM; i++)
#pragma unroll
        for (int j = 0; j < TN; j++) acc[i][j] = 0.f;

    int lr = tid >> 2;          // 0..63
    int lc = (tid & 3) * 4;     // 0,4,8,12
    int ty = tid >> 4;          // 0..15
    int tx = tid & 15;          // 0..15

    for (int k0 = 0; k0 < DD; k0 += BK) {
#pragma unroll
        for (int r = 0; r < 2; r++) {
            int row = lr + r * 64;
            float4 v = *(const float4*)(A + (size_t)row * DD + k0 + lc);
            As[lc + 0][row] = v.x * w3s[k0 + lc + 0];
            As[lc + 1][row] = v.y * w3s[k0 + lc + 1];
            As[lc + 2][row] = v.z * w3s[k0 + lc + 2];
            As[lc + 3][row] = v.w * w3s[k0 + lc + 3];
            float4 u = *(const float4*)(Bq + (size_t)row * DD + k0 + lc);
            Bs[lc + 0][row] = u.x;
            Bs[lc + 1][row] = u.y;
            Bs[lc + 2][row] = u.z;
            Bs[lc + 3][row] = u.w;
        }
        __syncthreads();
#pragma unroll
        for (int kk = 0; kk < BK; kk++) {
            float ra[TM], rb[TN];
#pragma unroll
            for (int i = 0; i < TM; i++) ra[i] = As[kk][ty * TM + i];
#pragma unroll
            for (int j = 0; j < TN; j++) rb[j] = Bs[kk][tx * TN + j];
#pragma unroll
            for (int i = 0; i < TM; i++)
#pragma unroll
                for (int j = 0; j < TN; j++) acc[i][j] += ra[i] * rb[j];
        }
        __syncthreads();
    }

    // epilogue: + a[m] + c[n], write S
    float am[TM], cn[TN];
#pragma unroll
    for (int i = 0; i < TM; i++) am[i] = g_a[b * TT + m0 + ty * TM + i];
#pragma unroll
    for (int j = 0; j < TN; j++) cn[j] = g_c[b * JJ + n0 + tx * TN + j];
    float* Sout = g_S + (size_t)b * TT * JJ;
#pragma unroll
    for (int i = 0; i < TM; i++) {
        int m = m0 + ty * TM + i;
#pragma unroll
        for (int j = 0; j < TN; j += 4) {
            float4 o;
            o.x = acc[i][j + 0] + am[i] + cn[j + 0];
            o.y = acc[i][j + 1] + am[i] + cn[j + 1];
            o.z = acc[i][j + 2] + am[i] + cn[j + 2];
            o.w = acc[i][j + 3] + am[i] + cn[j + 3];
            *(float4*)(Sout + (size_t)m * JJ + n0 + tx * TN + j) = o;
        }
    }
}

// ---------------------------------------------------------------------------
// K3: per (b,j) online softmax stats over t: colmax, 1/colsum
// ---------------------------------------------------------------------------
__global__ void colstats_kernel() {
    int b = blockIdx.x;
    int j = threadIdx.x;  // 256 threads = J columns
    const float* Sb = g_S + (size_t)b * TT * JJ;
    float m = -3.0e38f, s = 0.f;
#pragma unroll 4
    for (int t = 0; t < TT; t++) {
        float v = Sb[(size_t)t * JJ + j];
        if (v > m) {
            s = s * __expf(m - v) + 1.0f;
            m = v;
        } else {
            s += __expf(v - m);
        }
    }
    g_colmax[b * JJ + j] = m;
    g_cinv[b * JJ + j] = 1.0f / s;
}

// ---------------------------------------------------------------------------
// K4: rowmax[b,t] = max_j S[b,t,j]   (one warp per row)
// ---------------------------------------------------------------------------
__global__ void rowmax_kernel() {
    int row = (blockIdx.x * blockDim.x + threadIdx.x) >> 5;  // b*T + t
    int lane = threadIdx.x & 31;
    if (row >= BB * TT) return;
    const float* r = g_S + (size_t)row * JJ;
    float m = -3.0e38f;
#pragma unroll
    for (int k = lane * 4; k < JJ; k += 128) {
        float4 v = *(const float4*)(r + k);
        m = fmaxf(m, fmaxf(fmaxf(v.x, v.y), fmaxf(v.z, v.w)));
    }
#pragma unroll
    for (int o = 16; o; o >>= 1) m = fmaxf(m, __shfl_xor_sync(0xffffffffu, m, o));
    if (lane == 0) g_rowmax[row] = m;
}

// ---------------------------------------------------------------------------
// K5: b_t = softmax_t(rowmax[b,:]);  h[b,d] = sum_t b_t[t] * ctx[b,t,d]
// one block per b, 512 threads (= D)
// ---------------------------------------------------------------------------
__global__ __launch_bounds__(512) void bt_h_kernel(const float* __restrict__ ctx) {
    int b = blockIdx.x;
    int tid = threadIdx.x;
    __shared__ float e[TT];
    __shared__ float red[16];

    const float* rm = g_rowmax + b * TT;
    float v0 = rm[tid], v1 = rm[tid + 512];
    float m = fmaxf(v0, v1);
#pragma unroll
    for (int o = 16; o; o >>= 1) m = fmaxf(m, __shfl_xor_sync(0xffffffffu, m, o));
    if ((tid & 31) == 0) red[tid >> 5] = m;
    __syncthreads();
    if (tid < 32) {
        float x = (tid < 16) ? red[tid] : -3.0e38f;
#pragma unroll
        for (int o = 16; o; o >>= 1) x = fmaxf(x, __shfl_xor_sync(0xffffffffu, x, o));
        if (tid == 0) red[0] = x;
    }
    __syncthreads();
    float bm = red[0];
    __syncthreads();

    float e0 = __expf(v0 - bm), e1 = __expf(v1 - bm);
    e[tid] = e0;
    e[tid + 512] = e1;
    float s = e0 + e1;
#pragma unroll
    for (int o = 16; o; o >>= 1) s += __shfl_xor_sync(0xffffffffu, s, o);
    if ((tid & 31) == 0) red[tid >> 5] = s;
    __syncthreads();
    if (tid < 32) {
        float x = (tid < 16) ? red[tid] : 0.f;
#pragma unroll
        for (int o = 16; o; o >>= 1) x += __shfl_xor_sync(0xffffffffu, x, o);
        if (tid == 0) red[0] = x;
    }
    __syncthreads();
    float inv = 1.0f / red[0];

    // h[d], d = tid
    const float* cb = ctx + (size_t)b * TT * DD + tid;
    float a0 = 0.f, a1 = 0.f, a2 = 0.f, a3 = 0.f;
    for (int t = 0; t < TT; t += 4) {
        a0 += e[t + 0] * cb[(size_t)(t + 0) * DD];
        a1 += e[t + 1] * cb[(size_t)(t + 1) * DD];
        a2 += e[t + 2] * cb[(size_t)(t + 2) * DD];
        a3 += e[t + 3] * cb[(size_t)(t + 3) * DD];
    }
    g_h[b * DD + tid] = (a0 + a1 + a2 + a3) * inv;
}

// ---------------------------------------------------------------------------
// K6: U[b] = P[b] @ qry[b]   with P = exp(S - colmax)*cinv built in A-load.
// Fused epilogue writes G = [ctx, U, ctx*U, ctx*h]
// ---------------------------------------------------------------------------
__global__ __launch_bounds__(256, 2) void gemm2_kernel(
    const float* __restrict__ ctx, const float* __restrict__ qry,
    float* __restrict__ out) {
    __shared__ float As[BK][BM + PAD];
    __shared__ float Bs[BK][BN + PAD];
    __shared__ float cmS[JJ];
    __shared__ float ciS[JJ];

    int b = blockIdx.z;
    int m0 = blockIdx.y * BM;
    int n0 = blockIdx.x * BN;
    int tid = threadIdx.x;

    for (int i = tid; i < JJ; i += 256) {
        cmS[i] = g_colmax[b * JJ + i];
        ciS[i] = g_cinv[b * JJ + i];
    }
    __syncthreads();

    const float* A = g_S + ((size_t)b * TT + m0) * JJ;  // logits [m][k], ld=JJ
    const float* Bq = qry + (size_t)b * JJ * DD + n0;   // [k][n], ld=DD

    float acc[TM][TN];
#pragma unroll
    for (int i = 0; i < TM; i++)
#pragma unroll
        for (int j = 0; j < TN; j++) acc[i][j] = 0.f;

    int lr = tid >> 2;
    int lc = (tid & 3) * 4;
    int brow = tid >> 5;        // 0..7
    int bcol = (tid & 31) * 4;  // 0..124
    int ty = tid >> 4;
    int tx = tid & 15;

    for (int k0 = 0; k0 < JJ; k0 += BK) {
#pragma unroll
        for (int r = 0; r < 2; r++) {
            int row = lr + r * 64;
            float4 v = *(const float4*)(A + (size_t)row * JJ + k0 + lc);
            As[lc + 0][row] = __expf(v.x - cmS[k0 + lc + 0]) * ciS[k0 + lc + 0];
            As[lc + 1][row] = __expf(v.y - cmS[k0 + lc + 1]) * ciS[k0 + lc + 1];
            As[lc + 2][row] = __expf(v.z - cmS[k0 + lc + 2]) * ciS[k0 + lc + 2];
            As[lc + 3][row] = __expf(v.w - cmS[k0 + lc + 3]) * ciS[k0 + lc + 3];
        }
#pragma unroll
        for (int r = 0; r < 2; r++) {
            int kr = brow + r * 8;
            float4 u = *(const float4*)(Bq + (size_t)(k0 + kr) * DD + bcol);
            *(float4*)&Bs[kr][bcol] = u;
        }
        __syncthreads();
#pragma unroll
        for (int kk = 0; kk < BK; kk++) {
            float ra[TM], rb[TN];
#pragma unroll
            for (int i = 0; i < TM; i++) ra[i] = As[kk][ty * TM + i];
#pragma unroll
            for (int j = 0; j < TN; j++) rb[j] = Bs[kk][tx * TN + j];
#pragma unroll
            for (int i = 0; i < TM; i++)
#pragma unroll
                for (int j = 0; j < TN; j++) acc[i][j] += ra[i] * rb[j];
        }
        __syncthreads();
    }

    // Fused epilogue: G[b,t, 0:512]=ctx, 512:1024=U, 1024:1536=ctx*U, 1536:2048=ctx*h
    float hv[TN];
#pragma unroll
    for (int j = 0; j < TN; j++) hv[j] = g_h[b * DD + n0 + tx * TN + j];
#pragma unroll
    for (int i = 0; i < TM; i++) {
        int m = m0 + ty * TM + i;
        const float* crow = ctx + ((size_t)b * TT + m) * DD + n0 + tx * TN;
        float* orow = out + ((size_t)b * TT + m) * DOUT + n0 + tx * TN;
#pragma unroll
        for (int j = 0; j < TN; j += 4) {
            float4 c4 = *(const float4*)(crow + j);
            float4 u4;
            u4.x = acc[i][j + 0];
            u4.y = acc[i][j + 1];
            u4.z = acc[i][j + 2];
            u4.w = acc[i][j + 3];
            float4 cu;
            cu.x = c4.x * u4.x; cu.y = c4.y * u4.y;
            cu.z = c4.z * u4.z; cu.w = c4.w * u4.w;
            float4 ch;
            ch.x = c4.x * hv[j + 0]; ch.y = c4.y * hv[j + 1];
            ch.z = c4.z * hv[j + 2]; ch.w = c4.w * hv[j + 3];
            *(float4*)(orow + j) = c4;
            *(float4*)(orow + 512 + j) = u4;
            *(float4*)(orow + 1024 + j) = cu;
            *(float4*)(orow + 1536 + j) = ch;
        }
    }
}

// ---------------------------------------------------------------------------
extern "C" void kernel_launch(void* const* d_in, const int* in_sizes, int n_in,
                              void* d_out, int out_size) {
    const float* ctx = (const float*)d_in[0];
    const float* qry = (const float*)d_in[1];
    const float* w = (const float*)d_in[2];
    float* out = (float*)d_out;

    bias_kernel<<<(BB * TT + BB * JJ) / 8, 256>>>(ctx, qry, w);
    gemm1_kernel<<<dim3(JJ / BN, TT / BM, BB), 256>>>(ctx, qry, w);
    colstats_kernel<<<BB, JJ>>>();
    rowmax_kernel<<<BB * TT / 8, 256>>>();
    bt_h_kernel<<<BB, 512>>>(ctx);
    gemm2_kernel<<<dim3(DD / BN, TT / BM, BB), 256>>>(ctx, qry, out);
}

// round 6
// speedup vs baseline: 1.3572x; 1.3572x over previous
#include <cuda_runtime.h>
#include <cuda_bf16.h>
#include <mma.h>
#include <stdint.h>
#include <math.h>

using namespace nvcuda;

#define BB 32
#define TT 1024
#define JJ 256
#define DD 512

// ------------------- device scratch (no runtime alloc) ----------------------
__device__ float g_S[(size_t)BB * TT * JJ];
__device__ __nv_bfloat16 g_Ahi[(size_t)BB * TT * DD];  // split(ctx*w3)
__device__ __nv_bfloat16 g_Alo[(size_t)BB * TT * DD];
__device__ __nv_bfloat16 g_Bhi[(size_t)BB * JJ * DD];  // split(q) [b,j,d]
__device__ __nv_bfloat16 g_Blo[(size_t)BB * JJ * DD];
__device__ __nv_bfloat16 g_Thi[(size_t)BB * DD * JJ];  // split(q^T) [b,d,j]
__device__ __nv_bfloat16 g_Tlo[(size_t)BB * DD * JJ];
__device__ float g_a[BB * TT], g_c[BB * JJ];
__device__ float g_cm[BB * JJ], g_ci[BB * JJ];
__device__ float g_rm[BB * TT], g_h[BB * DD];
__device__ float g_pm[BB * 8 * JJ], g_ps[BB * 8 * JJ];

// ------------------------------ helpers -------------------------------------
__device__ __forceinline__ uint32_t smem_u32(const void* p) {
    uint32_t a;
    asm("{ .reg .u64 t; cvta.to.shared.u64 t, %1; cvt.u32.u64 %0, t; }"
        : "=r"(a) : "l"(p));
    return a;
}
__device__ __forceinline__ void cpa16(uint32_t d, const void* s) {
    asm volatile("cp.async.cg.shared.global [%0], [%1], 16;" :: "r"(d), "l"(s));
}
__device__ __forceinline__ void cpa_commit() {
    asm volatile("cp.async.commit_group;" ::: "memory");
}
template <int N>
__device__ __forceinline__ void cpa_wait() {
    asm volatile("cp.async.wait_group %0;" :: "n"(N) : "memory");
}

__device__ __forceinline__ void split4(float x0, float x1, float x2, float x3,
                                       uint2& hi, uint2& lo) {
    __nv_bfloat16 h0 = __float2bfloat16(x0), h1 = __float2bfloat16(x1);
    __nv_bfloat16 h2 = __float2bfloat16(x2), h3 = __float2bfloat16(x3);
    __nv_bfloat16 l0 = __float2bfloat16(x0 - __bfloat162float(h0));
    __nv_bfloat16 l1 = __float2bfloat16(x1 - __bfloat162float(h1));
    __nv_bfloat16 l2 = __float2bfloat16(x2 - __bfloat162float(h2));
    __nv_bfloat16 l3 = __float2bfloat16(x3 - __bfloat162float(h3));
    hi.x = ((uint32_t)__bfloat16_as_ushort(h1) << 16) | __bfloat16_as_ushort(h0);
    hi.y = ((uint32_t)__bfloat16_as_ushort(h3) << 16) | __bfloat16_as_ushort(h2);
    lo.x = ((uint32_t)__bfloat16_as_ushort(l1) << 16) | __bfloat16_as_ushort(l0);
    lo.y = ((uint32_t)__bfloat16_as_ushort(l3) << 16) | __bfloat16_as_ushort(l2);
}

// smem chunk layout (bytes, per buffer): Ahi@0 Alo@18432 Bhi@36864 Blo@55296
#define LDS 72
#define MAT_B 18432
#define BUF_B 73728
#define SMB1 (2 * BUF_B + 1024)
#define SMB2 (2 * BUF_B + 2560)

typedef wmma::fragment<wmma::accumulator, 16, 16, 16, float> AccFrag;
typedef wmma::fragment<wmma::matrix_a, 16, 16, 16, __nv_bfloat16, wmma::row_major> AFrag;
typedef wmma::fragment<wmma::matrix_b, 16, 16, 16, __nv_bfloat16, wmma::col_major> BFrag;

// compute one K=64 chunk: acc += Ah*Bh + Ah*Bl + Al*Bh  (warp tile 64x32)
__device__ __forceinline__ void compute_chunk(const char* smc, int boff,
                                              int wm, int wn, AccFrag acc[4][2]) {
    const __nv_bfloat16* Ah = (const __nv_bfloat16*)(smc + boff);
    const __nv_bfloat16* Al = (const __nv_bfloat16*)(smc + boff + MAT_B);
    const __nv_bfloat16* Bh = (const __nv_bfloat16*)(smc + boff + 2 * MAT_B);
    const __nv_bfloat16* Bl = (const __nv_bfloat16*)(smc + boff + 3 * MAT_B);
#pragma unroll
    for (int k0 = 0; k0 < 64; k0 += 16) {
        AFrag ah[4], al[4];
        BFrag bh[2], bl[2];
#pragma unroll
        for (int i = 0; i < 4; i++) {
            wmma::load_matrix_sync(ah[i], Ah + (wm * 64 + i * 16) * LDS + k0, LDS);
            wmma::load_matrix_sync(al[i], Al + (wm * 64 + i * 16) * LDS + k0, LDS);
        }
#pragma unroll
        for (int j = 0; j < 2; j++) {
            wmma::load_matrix_sync(bh[j], Bh + (wn * 32 + j * 16) * LDS + k0, LDS);
            wmma::load_matrix_sync(bl[j], Bl + (wn * 32 + j * 16) * LDS + k0, LDS);
        }
#pragma unroll
        for (int i = 0; i < 4; i++)
#pragma unroll
            for (int j = 0; j < 2; j++) {
                wmma::mma_sync(acc[i][j], ah[i], bh[j], acc[i][j]);
                wmma::mma_sync(acc[i][j], ah[i], bl[j], acc[i][j]);
                wmma::mma_sync(acc[i][j], al[i], bh[j], acc[i][j]);
            }
    }
}

// ---------------------------------------------------------------------------
// K1: split(ctx*w3)->Ahi/Alo + a=ctx.w1 ; split(q)->Bhi/Blo + c=q.w2
// ---------------------------------------------------------------------------
__global__ void convert_kernel(const float* __restrict__ ctx,
                               const float* __restrict__ qry,
                               const float* __restrict__ w) {
    int gw = (blockIdx.x * blockDim.x + threadIdx.x) >> 5;
    int lane = threadIdx.x & 31;
    if (gw < BB * TT) {
        const float* row = ctx + (size_t)gw * DD;
        float acc = 0.f;
#pragma unroll
        for (int i = 0; i < 4; i++) {
            int col = i * 128 + lane * 4;
            float4 x = *(const float4*)(row + col);
            float4 w1v = *(const float4*)(w + col);
            acc += x.x * w1v.x + x.y * w1v.y + x.z * w1v.z + x.w * w1v.w;
            float4 w3v = *(const float4*)(w + 2 * DD + col);
            uint2 hi, lo;
            split4(x.x * w3v.x, x.y * w3v.y, x.z * w3v.z, x.w * w3v.w, hi, lo);
            size_t o = (size_t)gw * DD + col;
            *(uint2*)((char*)g_Ahi + o * 2) = hi;
            *(uint2*)((char*)g_Alo + o * 2) = lo;
        }
#pragma unroll
        for (int o = 16; o; o >>= 1) acc += __shfl_xor_sync(~0u, acc, o);
        if (lane == 0) g_a[gw] = acc;
    } else {
        int r = gw - BB * TT;
        if (r >= BB * JJ) return;
        const float* row = qry + (size_t)r * DD;
        float acc = 0.f;
#pragma unroll
        for (int i = 0; i < 4; i++) {
            int col = i * 128 + lane * 4;
            float4 x = *(const float4*)(row + col);
            float4 w2v = *(const float4*)(w + DD + col);
            acc += x.x * w2v.x + x.y * w2v.y + x.z * w2v.z + x.w * w2v.w;
            uint2 hi, lo;
            split4(x.x, x.y, x.z, x.w, hi, lo);
            size_t o = (size_t)r * DD + col;
            *(uint2*)((char*)g_Bhi + o * 2) = hi;
            *(uint2*)((char*)g_Blo + o * 2) = lo;
        }
#pragma unroll
        for (int o = 16; o; o >>= 1) acc += __shfl_xor_sync(~0u, acc, o);
        if (lane == 0) g_c[r] = acc;
    }
}

// ---------------------------------------------------------------------------
// K2: q^T split -> Thi/Tlo [b,d,j]
// ---------------------------------------------------------------------------
__global__ void qt_kernel(const float* __restrict__ qry) {
    __shared__ float tile[32][33];
    int b = blockIdx.z, d0 = blockIdx.x * 32, j0 = blockIdx.y * 32;
    int tid = threadIdx.x;
    int r = tid >> 3, c4 = (tid & 7) * 4;
    float4 v = *(const float4*)(qry + ((size_t)b * JJ + j0 + r) * DD + d0 + c4);
    tile[r][c4 + 0] = v.x;
    tile[r][c4 + 1] = v.y;
    tile[r][c4 + 2] = v.z;
    tile[r][c4 + 3] = v.w;
    __syncthreads();
    uint2 hi, lo;
    split4(tile[c4 + 0][r], tile[c4 + 1][r], tile[c4 + 2][r], tile[c4 + 3][r], hi, lo);
    size_t o = ((size_t)b * DD + d0 + r) * JJ + j0 + c4;
    *(uint2*)((char*)g_Thi + o * 2) = hi;
    *(uint2*)((char*)g_Tlo + o * 2) = lo;
}

// ---------------------------------------------------------------------------
// K3: GEMM1 (WMMA): S[b, m0:+128, n0:+128] = (ctx*w3)@q^T + a + c
// ---------------------------------------------------------------------------
__global__ __launch_bounds__(256, 1) void gemm1_wmma() {
    extern __shared__ __align__(16) char smc[];
    int tid = threadIdx.x;
    int wid = tid >> 5, wm = wid >> 2, wn = wid & 3;
    int b = blockIdx.z, m0 = blockIdx.y * 128, n0 = blockIdx.x * 128;

    float* a_s = (float*)(smc + 2 * BUF_B);
    float* c_s = (float*)(smc + 2 * BUF_B + 512);
    if (tid < 128) {
        a_s[tid] = g_a[b * TT + m0 + tid];
        c_s[tid] = g_c[b * JJ + n0 + tid];
    }

    const __nv_bfloat16* Ah = g_Ahi + (size_t)(b * TT + m0) * DD;
    const __nv_bfloat16* Al = g_Alo + (size_t)(b * TT + m0) * DD;
    const __nv_bfloat16* Bh = g_Bhi + (size_t)(b * JJ + n0) * DD;
    const __nv_bfloat16* Bl = g_Blo + (size_t)(b * JJ + n0) * DD;
    uint32_t sm0 = smem_u32(smc);

    AccFrag acc[4][2];
#pragma unroll
    for (int i = 0; i < 4; i++)
#pragma unroll
        for (int j = 0; j < 2; j++) wmma::fill_fragment(acc[i][j], 0.f);

    // prologue: chunk 0
#pragma unroll 1
    for (int i = tid; i < 1024; i += 256) {
        int row = i >> 3, seg = (i & 7) * 8;
        size_t g = (size_t)row * DD + seg;
        uint32_t s = sm0 + (uint32_t)(row * LDS + seg) * 2;
        cpa16(s, Ah + g);
        cpa16(s + MAT_B, Al + g);
        cpa16(s + 2 * MAT_B, Bh + g);
        cpa16(s + 3 * MAT_B, Bl + g);
    }
    cpa_commit();

    for (int c = 0; c < 8; c++) {
        int cb = (c & 1) * BUF_B;
        if (c + 1 < 8) {
            int nb = ((c + 1) & 1) * BUF_B;
            int kc = (c + 1) * 64;
#pragma unroll 1
            for (int i = tid; i < 1024; i += 256) {
                int row = i >> 3, seg = (i & 7) * 8;
                size_t g = (size_t)row * DD + kc + seg;
                uint32_t s = sm0 + nb + (uint32_t)(row * LDS + seg) * 2;
                cpa16(s, Ah + g);
                cpa16(s + MAT_B, Al + g);
                cpa16(s + 2 * MAT_B, Bh + g);
                cpa16(s + 3 * MAT_B, Bl + g);
            }
            cpa_commit();
            cpa_wait<1>();
        } else {
            cpa_wait<0>();
        }
        __syncthreads();
        compute_chunk(smc, cb, wm, wn, acc);
        __syncthreads();
    }

    // epilogue: stage to smem, add bias, coalesced write
    float* Su = (float*)smc;
#pragma unroll
    for (int i = 0; i < 4; i++)
#pragma unroll
        for (int j = 0; j < 2; j++)
            wmma::store_matrix_sync(Su + (wm * 64 + i * 16) * 132 + wn * 32 + j * 16,
                                    acc[i][j], 132, wmma::mem_row_major);
    __syncthreads();
    int col4 = (tid & 31) * 4, r8 = tid >> 5;
    float* Sg = g_S + (size_t)(b * TT + m0) * JJ + n0;
#pragma unroll 1
    for (int r0 = 0; r0 < 128; r0 += 8) {
        int row = r0 + r8;
        float4 v = *(float4*)&Su[row * 132 + col4];
        float av = a_s[row];
        float4 cv = *(float4*)&c_s[col4];
        v.x += av + cv.x; v.y += av + cv.y; v.z += av + cv.z; v.w += av + cv.w;
        *(float4*)(Sg + (size_t)row * JJ + col4) = v;
    }
}

// ---------------------------------------------------------------------------
// K4: rowmax[b,t] = max_j S[b,t,j]
// ---------------------------------------------------------------------------
__global__ void rowmax_kernel() {
    int row = (blockIdx.x * blockDim.x + threadIdx.x) >> 5;
    int lane = threadIdx.x & 31;
    if (row >= BB * TT) return;
    const float* r = g_S + (size_t)row * JJ;
    float m = -3.0e38f;
#pragma unroll
    for (int k = lane * 4; k < JJ; k += 128) {
        float4 v = *(const float4*)(r + k);
        m = fmaxf(m, fmaxf(fmaxf(v.x, v.y), fmaxf(v.z, v.w)));
    }
#pragma unroll
    for (int o = 16; o; o >>= 1) m = fmaxf(m, __shfl_xor_sync(~0u, m, o));
    if (lane == 0) g_rm[row] = m;
}

// ---------------------------------------------------------------------------
// K5/K6: column softmax stats, split then combine
// ---------------------------------------------------------------------------
__global__ void colpart_kernel() {
    int b = blockIdx.y, part = blockIdx.x, j = threadIdx.x;
    const float* Sb = g_S + ((size_t)b * TT + part * 128) * JJ + j;
    float m = -3.0e38f, s = 0.f;
#pragma unroll 4
    for (int t = 0; t < 128; t++) {
        float v = Sb[(size_t)t * JJ];
        if (v > m) { s = s * __expf(m - v) + 1.f; m = v; }
        else s += __expf(v - m);
    }
    g_pm[(b * 8 + part) * JJ + j] = m;
    g_ps[(b * 8 + part) * JJ + j] = s;
}
__global__ void colcomb_kernel() {
    int b = blockIdx.x, j = threadIdx.x;
    float m = -3.0e38f;
#pragma unroll
    for (int p = 0; p < 8; p++) m = fmaxf(m, g_pm[(b * 8 + p) * JJ + j]);
    float s = 0.f;
#pragma unroll
    for (int p = 0; p < 8; p++)
        s += g_ps[(b * 8 + p) * JJ + j] * __expf(g_pm[(b * 8 + p) * JJ + j] - m);
    g_cm[b * JJ + j] = m;
    g_ci[b * JJ + j] = 1.f / s;
}

// ---------------------------------------------------------------------------
// K7: b_t = softmax_t(rowmax); h[b,d] = sum_t b_t * ctx
// ---------------------------------------------------------------------------
__global__ __launch_bounds__(128) void bth_kernel(const float* __restrict__ ctx) {
    int b = blockIdx.y, q = blockIdx.x, tid = threadIdx.x;
    int wid = tid >> 5, lane = tid & 31;
    __shared__ float e_s[TT];
    __shared__ float red_m[4], red_s[4];
    float v[8];
    float m = -3.0e38f;
#pragma unroll
    for (int i = 0; i < 8; i++) {
        v[i] = g_rm[b * TT + tid + i * 128];
        m = fmaxf(m, v[i]);
    }
#pragma unroll
    for (int o = 16; o; o >>= 1) m = fmaxf(m, __shfl_xor_sync(~0u, m, o));
    if (lane == 0) red_m[wid] = m;
    __syncthreads();
    m = fmaxf(fmaxf(red_m[0], red_m[1]), fmaxf(red_m[2], red_m[3]));
    float s = 0.f;
#pragma unroll
    for (int i = 0; i < 8; i++) {
        float e = __expf(v[i] - m);
        e_s[tid + i * 128] = e;
        s += e;
    }
#pragma unroll
    for (int o = 16; o; o >>= 1) s += __shfl_xor_sync(~0u, s, o);
    if (lane == 0) red_s[wid] = s;
    __syncthreads();
    float inv = 1.f / (red_s[0] + red_s[1] + red_s[2] + red_s[3]);
    int d = q * 128 + tid;
    const float* cb = ctx + (size_t)b * TT * DD + d;
    float a0 = 0.f, a1 = 0.f, a2 = 0.f, a3 = 0.f;
    for (int t = 0; t < TT; t += 4) {
        a0 += e_s[t + 0] * cb[(size_t)(t + 0) * DD];
        a1 += e_s[t + 1] * cb[(size_t)(t + 1) * DD];
        a2 += e_s[t + 2] * cb[(size_t)(t + 2) * DD];
        a3 += e_s[t + 3] * cb[(size_t)(t + 3) * DD];
    }
    g_h[b * DD + d] = (a0 + a1 + a2 + a3) * inv;
}

// ---------------------------------------------------------------------------
// K8: GEMM2 (WMMA): U = softmax_col(S) @ q ; fused G epilogue
// A = probs built on-the-fly from S; B = q^T (hi/lo) via cp.async
// ---------------------------------------------------------------------------
__global__ __launch_bounds__(256, 1) void gemm2_wmma(const float* __restrict__ ctx,
                                                     float* __restrict__ out) {
    extern __shared__ __align__(16) char smc[];
    int tid = threadIdx.x;
    int wid = tid >> 5, wm = wid >> 2, wn = wid & 3;
    int b = blockIdx.z, m0 = blockIdx.y * 128, n0 = blockIdx.x * 128;

    float* cm_s = (float*)(smc + 2 * BUF_B);
    float* ci_s = (float*)(smc + 2 * BUF_B + 1024);
    float* h_s = (float*)(smc + 2 * BUF_B + 2048);
    cm_s[tid] = g_cm[b * JJ + tid];
    ci_s[tid] = g_ci[b * JJ + tid];
    if (tid < 128) h_s[tid] = g_h[b * DD + n0 + tid];
    __syncthreads();

    const float* Sg = g_S + (size_t)(b * TT + m0) * JJ;
    const __nv_bfloat16* Th = g_Thi + (size_t)(b * DD + n0) * JJ;
    const __nv_bfloat16* Tl = g_Tlo + (size_t)(b * DD + n0) * JJ;
    uint32_t sm0 = smem_u32(smc);

    AccFrag acc[4][2];
#pragma unroll
    for (int i = 0; i < 4; i++)
#pragma unroll
        for (int j = 0; j < 2; j++) wmma::fill_fragment(acc[i][j], 0.f);

    // prologue chunk 0: B via cp.async, A (probs) computed
#pragma unroll 1
    for (int i = tid; i < 1024; i += 256) {
        int row = i >> 3, seg = (i & 7) * 8;
        size_t g = (size_t)row * JJ + seg;
        uint32_t s = sm0 + (uint32_t)(row * LDS + seg) * 2;
        cpa16(s + 2 * MAT_B, Th + g);
        cpa16(s + 3 * MAT_B, Tl + g);
    }
    cpa_commit();
#pragma unroll 1
    for (int i = tid; i < 2048; i += 256) {
        int row = i >> 4, c4 = (i & 15) * 4;
        float4 v = *(const float4*)(Sg + (size_t)row * JJ + c4);
        float p0 = __expf(v.x - cm_s[c4 + 0]) * ci_s[c4 + 0];
        float p1 = __expf(v.y - cm_s[c4 + 1]) * ci_s[c4 + 1];
        float p2 = __expf(v.z - cm_s[c4 + 2]) * ci_s[c4 + 2];
        float p3 = __expf(v.w - cm_s[c4 + 3]) * ci_s[c4 + 3];
        uint2 hi, lo;
        split4(p0, p1, p2, p3, hi, lo);
        *(uint2*)(smc + (row * LDS + c4) * 2) = hi;
        *(uint2*)(smc + MAT_B + (row * LDS + c4) * 2) = lo;
    }

    for (int c = 0; c < 4; c++) {
        int cb = (c & 1) * BUF_B;
        if (c + 1 < 4) {
            int nb = ((c + 1) & 1) * BUF_B;
            int kc = (c + 1) * 64;
#pragma unroll 1
            for (int i = tid; i < 1024; i += 256) {
                int row = i >> 3, seg = (i & 7) * 8;
                size_t g = (size_t)row * JJ + kc + seg;
                uint32_t s = sm0 + nb + (uint32_t)(row * LDS + seg) * 2;
                cpa16(s + 2 * MAT_B, Th + g);
                cpa16(s + 3 * MAT_B, Tl + g);
            }
            cpa_commit();
#pragma unroll 1
            for (int i = tid; i < 2048; i += 256) {
                int row = i >> 4, c4 = (i & 15) * 4;
                int jb = kc + c4;
                float4 v = *(const float4*)(Sg + (size_t)row * JJ + jb);
                float p0 = __expf(v.x - cm_s[jb + 0]) * ci_s[jb + 0];
                float p1 = __expf(v.y - cm_s[jb + 1]) * ci_s[jb + 1];
                float p2 = __expf(v.z - cm_s[jb + 2]) * ci_s[jb + 2];
                float p3 = __expf(v.w - cm_s[jb + 3]) * ci_s[jb + 3];
                uint2 hi, lo;
                split4(p0, p1, p2, p3, hi, lo);
                *(uint2*)(smc + nb + (row * LDS + c4) * 2) = hi;
                *(uint2*)(smc + nb + MAT_B + (row * LDS + c4) * 2) = lo;
            }
            cpa_wait<1>();
        } else {
            cpa_wait<0>();
        }
        __syncthreads();
        compute_chunk(smc, cb, wm, wn, acc);
        __syncthreads();
    }

    // epilogue: stage U, fused G = [ctx, U, ctx*U, ctx*h]
    float* Su = (float*)smc;
#pragma unroll
    for (int i = 0; i < 4; i++)
#pragma unroll
        for (int j = 0; j < 2; j++)
            wmma::store_matrix_sync(Su + (wm * 64 + i * 16) * 132 + wn * 32 + j * 16,
                                    acc[i][j], 132, wmma::mem_row_major);
    __syncthreads();
    int col4 = (tid & 31) * 4, r8 = tid >> 5;
#pragma unroll 1
    for (int r0 = 0; r0 < 128; r0 += 8) {
        int row = r0 + r8;
        float4 u = *(float4*)&Su[row * 132 + col4];
        float4 cx = *(const float4*)(ctx + (size_t)(b * TT + m0 + row) * DD + n0 + col4);
        float4 h4 = *(float4*)&h_s[col4];
        float* og = out + (size_t)(b * TT + m0 + row) * 2048 + n0 + col4;
        float4 cu, ch;
        cu.x = cx.x * u.x; cu.y = cx.y * u.y; cu.z = cx.z * u.z; cu.w = cx.w * u.w;
        ch.x = cx.x * h4.x; ch.y = cx.y * h4.y; ch.z = cx.z * h4.z; ch.w = cx.w * h4.w;
        *(float4*)(og) = cx;
        *(float4*)(og + 512) = u;
        *(float4*)(og + 1024) = cu;
        *(float4*)(og + 1536) = ch;
    }
}

// ---------------------------------------------------------------------------
extern "C" void kernel_launch(void* const* d_in, const int* in_sizes, int n_in,
                              void* d_out, int out_size) {
    const float* ctx = (const float*)d_in[0];
    const float* qry = (const float*)d_in[1];
    const float* w = (const float*)d_in[2];
    float* out = (float*)d_out;

    cudaFuncSetAttribute(gemm1_wmma, cudaFuncAttributeMaxDynamicSharedMemorySize, SMB1);
    cudaFuncSetAttribute(gemm2_wmma, cudaFuncAttributeMaxDynamicSharedMemorySize, SMB2);

    convert_kernel<<<(BB * TT + BB * JJ) / 8, 256>>>(ctx, qry, w);
    qt_kernel<<<dim3(DD / 32, JJ / 32, BB), 256>>>(qry);
    gemm1_wmma<<<dim3(JJ / 128, TT / 128, BB), 256, SMB1>>>();
    rowmax_kernel<<<BB * TT / 8, 256>>>();
    colpart_kernel<<<dim3(8, BB), 256>>>();
    colcomb_kernel<<<BB, 256>>>();
    bth_kernel<<<dim3(4, BB), 128>>>(ctx);
    gemm2_wmma<<<dim3(DD / 128, TT / 128, BB), 256, SMB2>>>(ctx, out);
}

// round 7
// speedup vs baseline: 1.4893x; 1.0974x over previous
#include <cuda_runtime.h>
#include <cuda_bf16.h>
#include <mma.h>
#include <stdint.h>
#include <math.h>

using namespace nvcuda;

#define BB 32
#define TT 1024
#define JJ 256
#define DD 512

// ------------------- device scratch (no runtime alloc) ----------------------
__device__ float g_S[(size_t)BB * TT * JJ];
__device__ __nv_bfloat16 g_Ahi[(size_t)BB * TT * DD];  // split(ctx*w3)
__device__ __nv_bfloat16 g_Alo[(size_t)BB * TT * DD];
__device__ __nv_bfloat16 g_Bhi[(size_t)BB * JJ * DD];  // split(q) [b,j,d]
__device__ __nv_bfloat16 g_Blo[(size_t)BB * JJ * DD];
__device__ float g_a[BB * TT], g_c[BB * JJ];
__device__ float g_cm[BB * JJ], g_ci[BB * JJ];
__device__ unsigned int g_rmu[BB * TT];
__device__ float g_h[BB * DD];
__device__ float g_pm[BB * 8 * JJ], g_ps[BB * 8 * JJ];

// ------------------------------ helpers -------------------------------------
__device__ __forceinline__ uint32_t smem_u32(const void* p) {
    uint32_t a;
    asm("{ .reg .u64 t; cvta.to.shared.u64 t, %1; cvt.u32.u64 %0, t; }"
        : "=r"(a) : "l"(p));
    return a;
}
__device__ __forceinline__ void cpa16(uint32_t d, const void* s) {
    asm volatile("cp.async.cg.shared.global [%0], [%1], 16;" :: "r"(d), "l"(s));
}
__device__ __forceinline__ void cpa_commit() {
    asm volatile("cp.async.commit_group;" ::: "memory");
}
template <int N>
__device__ __forceinline__ void cpa_wait() {
    asm volatile("cp.async.wait_group %0;" :: "n"(N) : "memory");
}

// monotonic float<->uint encoding for atomicMax on signed floats
__device__ __forceinline__ unsigned int enc_f(float f) {
    unsigned int b = __float_as_uint(f);
    return (b & 0x80000000u) ? ~b : (b | 0x80000000u);
}
__device__ __forceinline__ float dec_f(unsigned int e) {
    unsigned int b = (e & 0x80000000u) ? (e & 0x7fffffffu) : ~e;
    return __uint_as_float(b);
}

__device__ __forceinline__ void split4(float x0, float x1, float x2, float x3,
                                       uint2& hi, uint2& lo) {
    __nv_bfloat16 h0 = __float2bfloat16(x0), h1 = __float2bfloat16(x1);
    __nv_bfloat16 h2 = __float2bfloat16(x2), h3 = __float2bfloat16(x3);
    __nv_bfloat16 l0 = __float2bfloat16(x0 - __bfloat162float(h0));
    __nv_bfloat16 l1 = __float2bfloat16(x1 - __bfloat162float(h1));
    __nv_bfloat16 l2 = __float2bfloat16(x2 - __bfloat162float(h2));
    __nv_bfloat16 l3 = __float2bfloat16(x3 - __bfloat162float(h3));
    hi.x = ((uint32_t)__bfloat16_as_ushort(h1) << 16) | __bfloat16_as_ushort(h0);
    hi.y = ((uint32_t)__bfloat16_as_ushort(h3) << 16) | __bfloat16_as_ushort(h2);
    lo.x = ((uint32_t)__bfloat16_as_ushort(l1) << 16) | __bfloat16_as_ushort(l0);
    lo.y = ((uint32_t)__bfloat16_as_ushort(l3) << 16) | __bfloat16_as_ushort(l2);
}

// layout constants
#define LDSA 40       // elements: 32 k + 8 pad (80B rows)
#define MATB1 10240   // 128*40*2 bytes
#define STG1 40960    // 4 matrices per stage
#define LDSB2 136     // elements: 128 n + 8 pad (272B rows)
#define MATB2 8704    // 32*136*2
#define STG2 37888    // 2*10240 (A hi/lo) + 2*8704 (B hi/lo)
#define SMB1 (2 * STG1 + 1024)
#define SMB2 (2 * STG2 + 3072)

typedef wmma::fragment<wmma::accumulator, 16, 16, 16, float> AccFrag;
typedef wmma::fragment<wmma::matrix_a, 16, 16, 16, __nv_bfloat16, wmma::row_major> AFrag;
typedef wmma::fragment<wmma::matrix_b, 16, 16, 16, __nv_bfloat16, wmma::col_major> BFragC;
typedef wmma::fragment<wmma::matrix_b, 16, 16, 16, __nv_bfloat16, wmma::row_major> BFragR;

// one K=32 chunk, gemm1 flavor (B col-major [n][k])
__device__ __forceinline__ void chunk_g1(const char* smc, int bo, int wm, int wn,
                                         AccFrag acc[2][2]) {
    const __nv_bfloat16* Ah = (const __nv_bfloat16*)(smc + bo);
    const __nv_bfloat16* Al = (const __nv_bfloat16*)(smc + bo + MATB1);
    const __nv_bfloat16* Bh = (const __nv_bfloat16*)(smc + bo + 2 * MATB1);
    const __nv_bfloat16* Bl = (const __nv_bfloat16*)(smc + bo + 3 * MATB1);
#pragma unroll
    for (int k0 = 0; k0 < 32; k0 += 16) {
        AFrag ah[2];
        BFragC bh[2];
#pragma unroll
        for (int i = 0; i < 2; i++)
            wmma::load_matrix_sync(ah[i], Ah + (wm * 32 + i * 16) * LDSA + k0, LDSA);
#pragma unroll
        for (int j = 0; j < 2; j++)
            wmma::load_matrix_sync(bh[j], Bh + (wn * 32 + j * 16) * LDSA + k0, LDSA);
#pragma unroll
        for (int i = 0; i < 2; i++)
#pragma unroll
            for (int j = 0; j < 2; j++) wmma::mma_sync(acc[i][j], ah[i], bh[j], acc[i][j]);
        BFragC bl[2];
#pragma unroll
        for (int j = 0; j < 2; j++)
            wmma::load_matrix_sync(bl[j], Bl + (wn * 32 + j * 16) * LDSA + k0, LDSA);
#pragma unroll
        for (int i = 0; i < 2; i++)
#pragma unroll
            for (int j = 0; j < 2; j++) wmma::mma_sync(acc[i][j], ah[i], bl[j], acc[i][j]);
        AFrag al[2];
#pragma unroll
        for (int i = 0; i < 2; i++)
            wmma::load_matrix_sync(al[i], Al + (wm * 32 + i * 16) * LDSA + k0, LDSA);
#pragma unroll
        for (int i = 0; i < 2; i++)
#pragma unroll
            for (int j = 0; j < 2; j++) wmma::mma_sync(acc[i][j], al[i], bh[j], acc[i][j]);
    }
}

// one K=32 chunk, gemm2 flavor (B row-major [k][n])
__device__ __forceinline__ void chunk_g2(const char* smc, int bo, int wm, int wn,
                                         AccFrag acc[2][2]) {
    const __nv_bfloat16* Ah = (const __nv_bfloat16*)(smc + bo);
    const __nv_bfloat16* Al = (const __nv_bfloat16*)(smc + bo + MATB1);
    const __nv_bfloat16* Bh = (const __nv_bfloat16*)(smc + bo + 2 * MATB1);
    const __nv_bfloat16* Bl = (const __nv_bfloat16*)(smc + bo + 2 * MATB1 + MATB2);
#pragma unroll
    for (int k0 = 0; k0 < 32; k0 += 16) {
        AFrag ah[2];
        BFragR bh[2];
#pragma unroll
        for (int i = 0; i < 2; i++)
            wmma::load_matrix_sync(ah[i], Ah + (wm * 32 + i * 16) * LDSA + k0, LDSA);
#pragma unroll
        for (int j = 0; j < 2; j++)
            wmma::load_matrix_sync(bh[j], Bh + k0 * LDSB2 + wn * 32 + j * 16, LDSB2);
#pragma unroll
        for (int i = 0; i < 2; i++)
#pragma unroll
            for (int j = 0; j < 2; j++) wmma::mma_sync(acc[i][j], ah[i], bh[j], acc[i][j]);
        BFragR bl[2];
#pragma unroll
        for (int j = 0; j < 2; j++)
            wmma::load_matrix_sync(bl[j], Bl + k0 * LDSB2 + wn * 32 + j * 16, LDSB2);
#pragma unroll
        for (int i = 0; i < 2; i++)
#pragma unroll
            for (int j = 0; j < 2; j++) wmma::mma_sync(acc[i][j], ah[i], bl[j], acc[i][j]);
        AFrag al[2];
#pragma unroll
        for (int i = 0; i < 2; i++)
            wmma::load_matrix_sync(al[i], Al + (wm * 32 + i * 16) * LDSA + k0, LDSA);
#pragma unroll
        for (int i = 0; i < 2; i++)
#pragma unroll
            for (int j = 0; j < 2; j++) wmma::mma_sync(acc[i][j], al[i], bh[j], acc[i][j]);
    }
}

// ---------------------------------------------------------------------------
// K1: split(ctx*w3)->Ahi/Alo + a=ctx.w1 ; split(q)->Bhi/Blo + c=q.w2
//     also init g_rmu to enc(-inf)=0
// ---------------------------------------------------------------------------
__global__ void convert_kernel(const float* __restrict__ ctx,
                               const float* __restrict__ qry,
                               const float* __restrict__ w) {
    int gw = (blockIdx.x * blockDim.x + threadIdx.x) >> 5;
    int lane = threadIdx.x & 31;
    if (gw < BB * TT) {
        const float* row = ctx + (size_t)gw * DD;
        float acc = 0.f;
#pragma unroll
        for (int i = 0; i < 4; i++) {
            int col = i * 128 + lane * 4;
            float4 x = *(const float4*)(row + col);
            float4 w1v = *(const float4*)(w + col);
            acc += x.x * w1v.x + x.y * w1v.y + x.z * w1v.z + x.w * w1v.w;
            float4 w3v = *(const float4*)(w + 2 * DD + col);
            uint2 hi, lo;
            split4(x.x * w3v.x, x.y * w3v.y, x.z * w3v.z, x.w * w3v.w, hi, lo);
            size_t o = (size_t)gw * DD + col;
            *(uint2*)((char*)g_Ahi + o * 2) = hi;
            *(uint2*)((char*)g_Alo + o * 2) = lo;
        }
#pragma unroll
        for (int o = 16; o; o >>= 1) acc += __shfl_xor_sync(~0u, acc, o);
        if (lane == 0) {
            g_a[gw] = acc;
            g_rmu[gw] = 0u;
        }
    } else {
        int r = gw - BB * TT;
        if (r >= BB * JJ) return;
        const float* row = qry + (size_t)r * DD;
        float acc = 0.f;
#pragma unroll
        for (int i = 0; i < 4; i++) {
            int col = i * 128 + lane * 4;
            float4 x = *(const float4*)(row + col);
            float4 w2v = *(const float4*)(w + DD + col);
            acc += x.x * w2v.x + x.y * w2v.y + x.z * w2v.z + x.w * w2v.w;
            uint2 hi, lo;
            split4(x.x, x.y, x.z, x.w, hi, lo);
            size_t o = (size_t)r * DD + col;
            *(uint2*)((char*)g_Bhi + o * 2) = hi;
            *(uint2*)((char*)g_Blo + o * 2) = lo;
        }
#pragma unroll
        for (int o = 16; o; o >>= 1) acc += __shfl_xor_sync(~0u, acc, o);
        if (lane == 0) g_c[r] = acc;
    }
}

// ---------------------------------------------------------------------------
// K2: GEMM1 (WMMA, 512 thr, 16 warps): S tile 128x128 = (ctx*w3)@q^T + a + c
//     fused rowmax via atomicMax(enc)
// ---------------------------------------------------------------------------
__global__ __launch_bounds__(512) void gemm1_wmma() {
    extern __shared__ __align__(16) char smc[];
    int tid = threadIdx.x;
    int wid = tid >> 5, wm = wid >> 2, wn = wid & 3;
    int b = blockIdx.z, m0 = blockIdx.y * 128, n0 = blockIdx.x * 128;

    float* a_s = (float*)(smc + 2 * STG1);
    float* c_s = (float*)(smc + 2 * STG1 + 512);
    if (tid < 128) {
        a_s[tid] = g_a[b * TT + m0 + tid];
        c_s[tid] = g_c[b * JJ + n0 + tid];
    }

    const __nv_bfloat16* Ah = g_Ahi + (size_t)(b * TT + m0) * DD;
    const __nv_bfloat16* Al = g_Alo + (size_t)(b * TT + m0) * DD;
    const __nv_bfloat16* Bh = g_Bhi + (size_t)(b * JJ + n0) * DD;
    const __nv_bfloat16* Bl = g_Blo + (size_t)(b * JJ + n0) * DD;
    uint32_t sm0 = smem_u32(smc);

    AccFrag acc[2][2];
#pragma unroll
    for (int i = 0; i < 2; i++)
#pragma unroll
        for (int j = 0; j < 2; j++) wmma::fill_fragment(acc[i][j], 0.f);

    // stage loader: 2048 cpa16 per stage (A hi/lo + B hi/lo)
    auto load_stage = [&](int stg, int kc) {
#pragma unroll 1
        for (int i = tid; i < 1024; i += 512) {
            int which = i >> 9, idx = i & 511;
            int row = idx >> 2, seg = idx & 3;
            const __nv_bfloat16* src = (which ? Al : Ah) + (size_t)row * DD + kc + seg * 8;
            cpa16(sm0 + stg + which * MATB1 + row * 80 + seg * 16, src);
        }
#pragma unroll 1
        for (int i = tid; i < 1024; i += 512) {
            int which = i >> 9, idx = i & 511;
            int row = idx >> 2, seg = idx & 3;
            const __nv_bfloat16* src = (which ? Bl : Bh) + (size_t)row * DD + kc + seg * 8;
            cpa16(sm0 + stg + 2 * MATB1 + which * MATB1 + row * 80 + seg * 16, src);
        }
        cpa_commit();
    };

    load_stage(0, 0);
    for (int c = 0; c < 16; c++) {
        int cb = (c & 1) * STG1;
        if (c + 1 < 16) {
            load_stage(((c + 1) & 1) * STG1, (c + 1) * 32);
            cpa_wait<1>();
        } else {
            cpa_wait<0>();
        }
        __syncthreads();
        chunk_g1(smc, cb, wm, wn, acc);
        __syncthreads();
    }

    // epilogue: stage to smem, bias, coalesced write + fused rowmax
    float* Su = (float*)smc;
#pragma unroll
    for (int i = 0; i < 2; i++)
#pragma unroll
        for (int j = 0; j < 2; j++)
            wmma::store_matrix_sync(Su + (wm * 32 + i * 16) * 132 + wn * 32 + j * 16,
                                    acc[i][j], 132, wmma::mem_row_major);
    __syncthreads();
    int col4 = (tid & 31) * 4, wr = tid >> 5;
    float* Sg = g_S + (size_t)(b * TT + m0) * JJ + n0;
#pragma unroll 1
    for (int r0 = 0; r0 < 128; r0 += 16) {
        int row = r0 + wr;
        float4 v = *(float4*)&Su[row * 132 + col4];
        float av = a_s[row];
        float4 cv = *(float4*)&c_s[col4];
        v.x += av + cv.x; v.y += av + cv.y; v.z += av + cv.z; v.w += av + cv.w;
        *(float4*)(Sg + (size_t)row * JJ + col4) = v;
        float rm = fmaxf(fmaxf(v.x, v.y), fmaxf(v.z, v.w));
#pragma unroll
        for (int o = 16; o; o >>= 1) rm = fmaxf(rm, __shfl_xor_sync(~0u, rm, o));
        if ((tid & 31) == 0) atomicMax(&g_rmu[b * TT + m0 + row], enc_f(rm));
    }
}

// ---------------------------------------------------------------------------
// K3/K4: column softmax stats, split then combine
// ---------------------------------------------------------------------------
__global__ void colpart_kernel() {
    int b = blockIdx.y, part = blockIdx.x, j = threadIdx.x;
    const float* Sb = g_S + ((size_t)b * TT + part * 128) * JJ + j;
    float m = -3.0e38f, s = 0.f;
#pragma unroll 4
    for (int t = 0; t < 128; t++) {
        float v = Sb[(size_t)t * JJ];
        if (v > m) { s = s * __expf(m - v) + 1.f; m = v; }
        else s += __expf(v - m);
    }
    g_pm[(b * 8 + part) * JJ + j] = m;
    g_ps[(b * 8 + part) * JJ + j] = s;
}
__global__ void colcomb_kernel() {
    int b = blockIdx.x, j = threadIdx.x;
    float m = -3.0e38f;
#pragma unroll
    for (int p = 0; p < 8; p++) m = fmaxf(m, g_pm[(b * 8 + p) * JJ + j]);
    float s = 0.f;
#pragma unroll
    for (int p = 0; p < 8; p++)
        s += g_ps[(b * 8 + p) * JJ + j] * __expf(g_pm[(b * 8 + p) * JJ + j] - m);
    g_cm[b * JJ + j] = m;
    g_ci[b * JJ + j] = 1.f / s;
}

// ---------------------------------------------------------------------------
// K5: b_t = softmax_t(rowmax); h[b,d] = sum_t b_t * ctx
// ---------------------------------------------------------------------------
__global__ __launch_bounds__(128) void bth_kernel(const float* __restrict__ ctx) {
    int b = blockIdx.y, q = blockIdx.x, tid = threadIdx.x;
    int wid = tid >> 5, lane = tid & 31;
    __shared__ float e_s[TT];
    __shared__ float red_m[4], red_s[4];
    float v[8];
    float m = -3.0e38f;
#pragma unroll
    for (int i = 0; i < 8; i++) {
        v[i] = dec_f(g_rmu[b * TT + tid + i * 128]);
        m = fmaxf(m, v[i]);
    }
#pragma unroll
    for (int o = 16; o; o >>= 1) m = fmaxf(m, __shfl_xor_sync(~0u, m, o));
    if (lane == 0) red_m[wid] = m;
    __syncthreads();
    m = fmaxf(fmaxf(red_m[0], red_m[1]), fmaxf(red_m[2], red_m[3]));
    float s = 0.f;
#pragma unroll
    for (int i = 0; i < 8; i++) {
        float e = __expf(v[i] - m);
        e_s[tid + i * 128] = e;
        s += e;
    }
#pragma unroll
    for (int o = 16; o; o >>= 1) s += __shfl_xor_sync(~0u, s, o);
    if (lane == 0) red_s[wid] = s;
    __syncthreads();
    float inv = 1.f / (red_s[0] + red_s[1] + red_s[2] + red_s[3]);
    int d = q * 128 + tid;
    const float* cb = ctx + (size_t)b * TT * DD + d;
    float a0 = 0.f, a1 = 0.f, a2 = 0.f, a3 = 0.f;
    for (int t = 0; t < TT; t += 4) {
        a0 += e_s[t + 0] * cb[(size_t)(t + 0) * DD];
        a1 += e_s[t + 1] * cb[(size_t)(t + 1) * DD];
        a2 += e_s[t + 2] * cb[(size_t)(t + 2) * DD];
        a3 += e_s[t + 3] * cb[(size_t)(t + 3) * DD];
    }
    g_h[b * DD + d] = (a0 + a1 + a2 + a3) * inv;
}

// ---------------------------------------------------------------------------
// K6: GEMM2 (WMMA, 512 thr): U = softmax_col(S) @ q ; fused G epilogue
// A = probs computed on the fly; B = q rows (row-major frags) via cp.async
// ---------------------------------------------------------------------------
__global__ __launch_bounds__(512) void gemm2_wmma(const float* __restrict__ ctx,
                                                  float* __restrict__ out) {
    extern __shared__ __align__(16) char smc[];
    int tid = threadIdx.x;
    int wid = tid >> 5, wm = wid >> 2, wn = wid & 3;
    int b = blockIdx.z, m0 = blockIdx.y * 128, n0 = blockIdx.x * 128;

    float* cm_s = (float*)(smc + 2 * STG2);
    float* ci_s = (float*)(smc + 2 * STG2 + 1024);
    float* h_s = (float*)(smc + 2 * STG2 + 2048);
    if (tid < 256) {
        cm_s[tid] = g_cm[b * JJ + tid];
        ci_s[tid] = g_ci[b * JJ + tid];
    } else if (tid < 384) {
        h_s[tid - 256] = g_h[b * DD + n0 + tid - 256];
    }
    __syncthreads();

    const float* Sg = g_S + (size_t)(b * TT + m0) * JJ;
    const __nv_bfloat16* Bh = g_Bhi + (size_t)b * JJ * DD + n0;
    const __nv_bfloat16* Bl = g_Blo + (size_t)b * JJ * DD + n0;
    uint32_t sm0 = smem_u32(smc);

    AccFrag acc[2][2];
#pragma unroll
    for (int i = 0; i < 2; i++)
#pragma unroll
        for (int j = 0; j < 2; j++) wmma::fill_fragment(acc[i][j], 0.f);

    // per-stage: A probs via LDG+STS; B (q rows kc..kc+32) via cp.async
    auto load_stage = [&](int stg, int kc) {
#pragma unroll 1
        for (int i = tid; i < 1024; i += 512) {
            int which = i >> 9, idx = i & 511;
            int row = idx >> 4, seg = idx & 15;
            const __nv_bfloat16* src =
                (which ? Bl : Bh) + (size_t)(kc + row) * DD + seg * 8;
            cpa16(sm0 + stg + 2 * MATB1 + which * MATB2 + row * 272 + seg * 16, src);
        }
        cpa_commit();
#pragma unroll 1
        for (int i = tid; i < 1024; i += 512) {
            int row = i >> 3, c4 = (i & 7) * 4;
            int jb = kc + c4;
            float4 v = *(const float4*)(Sg + (size_t)row * JJ + jb);
            float p0 = __expf(v.x - cm_s[jb + 0]) * ci_s[jb + 0];
            float p1 = __expf(v.y - cm_s[jb + 1]) * ci_s[jb + 1];
            float p2 = __expf(v.z - cm_s[jb + 2]) * ci_s[jb + 2];
            float p3 = __expf(v.w - cm_s[jb + 3]) * ci_s[jb + 3];
            uint2 hi, lo;
            split4(p0, p1, p2, p3, hi, lo);
            *(uint2*)(smc + stg + row * 80 + c4 * 2) = hi;
            *(uint2*)(smc + stg + MATB1 + row * 80 + c4 * 2) = lo;
        }
    };

    load_stage(0, 0);
    for (int c = 0; c < 8; c++) {
        int cb = (c & 1) * STG2;
        if (c + 1 < 8) {
            load_stage(((c + 1) & 1) * STG2, (c + 1) * 32);
            cpa_wait<1>();
        } else {
            cpa_wait<0>();
        }
        __syncthreads();
        chunk_g2(smc, cb, wm, wn, acc);
        __syncthreads();
    }

    // epilogue: stage U, fused G = [ctx, U, ctx*U, ctx*h]
    float* Su = (float*)smc;
#pragma unroll
    for (int i = 0; i < 2; i++)
#pragma unroll
        for (int j = 0; j < 2; j++)
            wmma::store_matrix_sync(Su + (wm * 32 + i * 16) * 132 + wn * 32 + j * 16,
                                    acc[i][j], 132, wmma::mem_row_major);
    __syncthreads();
    int col4 = (tid & 31) * 4, wr = tid >> 5;
#pragma unroll 1
    for (int r0 = 0; r0 < 128; r0 += 16) {
        int row = r0 + wr;
        float4 u = *(float4*)&Su[row * 132 + col4];
        float4 cx = *(const float4*)(ctx + (size_t)(b * TT + m0 + row) * DD + n0 + col4);
        float4 h4 = *(float4*)&h_s[col4];
        float* og = out + (size_t)(b * TT + m0 + row) * 2048 + n0 + col4;
        float4 cu, ch;
        cu.x = cx.x * u.x; cu.y = cx.y * u.y; cu.z = cx.z * u.z; cu.w = cx.w * u.w;
        ch.x = cx.x * h4.x; ch.y = cx.y * h4.y; ch.z = cx.z * h4.z; ch.w = cx.w * h4.w;
        *(float4*)(og) = cx;
        *(float4*)(og + 512) = u;
        *(float4*)(og + 1024) = cu;
        *(float4*)(og + 1536) = ch;
    }
}

// ---------------------------------------------------------------------------
extern "C" void kernel_launch(void* const* d_in, const int* in_sizes, int n_in,
                              void* d_out, int out_size) {
    const float* ctx = (const float*)d_in[0];
    const float* qry = (const float*)d_in[1];
    const float* w = (const float*)d_in[2];
    float* out = (float*)d_out;

    cudaFuncSetAttribute(gemm1_wmma, cudaFuncAttributeMaxDynamicSharedMemorySize, SMB1);
    cudaFuncSetAttribute(gemm2_wmma, cudaFuncAttributeMaxDynamicSharedMemorySize, SMB2);

    convert_kernel<<<(BB * TT + BB * JJ) / 8, 256>>>(ctx, qry, w);
    gemm1_wmma<<<dim3(JJ / 128, TT / 128, BB), 512, SMB1>>>();
    colpart_kernel<<<dim3(8, BB), 256>>>();
    colcomb_kernel<<<BB, 256>>>();
    bth_kernel<<<dim3(4, BB), 128>>>(ctx);
    gemm2_wmma<<<dim3(DD / 128, TT / 128, BB), 512, SMB2>>>(ctx, out);
}

// round 9
// speedup vs baseline: 1.5595x; 1.0471x over previous
#include <cuda_runtime.h>
#include <cuda_bf16.h>
#include <mma.h>
#include <stdint.h>
#include <math.h>

using namespace nvcuda;

#define BB 32
#define TT 1024
#define JJ 256
#define DD 512

// ------------------- device scratch (no runtime alloc) ----------------------
__device__ float g_S[(size_t)BB * TT * JJ];
__device__ __nv_bfloat16 g_Ahi[(size_t)BB * TT * DD];  // split(ctx*w3)
__device__ __nv_bfloat16 g_Alo[(size_t)BB * TT * DD];
__device__ __nv_bfloat16 g_Bhi[(size_t)BB * JJ * DD];  // split(q) [b,j,d]
__device__ __nv_bfloat16 g_Blo[(size_t)BB * JJ * DD];
__device__ float g_a[BB * TT], g_c[BB * JJ];
__device__ unsigned int g_rmu[BB * TT];
__device__ float g_h[BB * DD];
__device__ float g_pm[BB * 8 * JJ], g_ps[BB * 8 * JJ];

// ------------------------------ helpers -------------------------------------
__device__ __forceinline__ uint32_t smem_u32(const void* p) {
    uint32_t a;
    asm("{ .reg .u64 t; cvta.to.shared.u64 t, %1; cvt.u32.u64 %0, t; }"
        : "=r"(a) : "l"(p));
    return a;
}
__device__ __forceinline__ void cpa16(uint32_t d, const void* s) {
    asm volatile("cp.async.cg.shared.global [%0], [%1], 16;" :: "r"(d), "l"(s));
}
__device__ __forceinline__ void cpa_commit() {
    asm volatile("cp.async.commit_group;" ::: "memory");
}
template <int N>
__device__ __forceinline__ void cpa_wait() {
    asm volatile("cp.async.wait_group %0;" :: "n"(N) : "memory");
}

// monotonic float<->uint encoding for atomicMax on signed floats
__device__ __forceinline__ unsigned int enc_f(float f) {
    unsigned int b = __float_as_uint(f);
    return (b & 0x80000000u) ? ~b : (b | 0x80000000u);
}
__device__ __forceinline__ float dec_f(unsigned int e) {
    unsigned int b = (e & 0x80000000u) ? (e & 0x7fffffffu) : ~e;
    return __uint_as_float(b);
}

__device__ __forceinline__ void split4(float x0, float x1, float x2, float x3,
                                       uint2& hi, uint2& lo) {
    __nv_bfloat16 h0 = __float2bfloat16(x0), h1 = __float2bfloat16(x1);
    __nv_bfloat16 h2 = __float2bfloat16(x2), h3 = __float2bfloat16(x3);
    __nv_bfloat16 l0 = __float2bfloat16(x0 - __bfloat162float(h0));
    __nv_bfloat16 l1 = __float2bfloat16(x1 - __bfloat162float(h1));
    __nv_bfloat16 l2 = __float2bfloat16(x2 - __bfloat162float(h2));
    __nv_bfloat16 l3 = __float2bfloat16(x3 - __bfloat162float(h3));
    hi.x = ((uint32_t)__bfloat16_as_ushort(h1) << 16) | __bfloat16_as_ushort(h0);
    hi.y = ((uint32_t)__bfloat16_as_ushort(h3) << 16) | __bfloat16_as_ushort(h2);
    lo.x = ((uint32_t)__bfloat16_as_ushort(l1) << 16) | __bfloat16_as_ushort(l0);
    lo.y = ((uint32_t)__bfloat16_as_ushort(l3) << 16) | __bfloat16_as_ushort(l2);
}

// layout constants
#define LDSA 40       // elements: 32 k + 8 pad (80B rows)
#define MATB1 10240   // 128*40*2 bytes
#define STG1 40960    // 4 matrices per stage (A hi/lo, B hi/lo)
#define LDSB2 136     // elements: 128 n + 8 pad (272B rows)
#define MATB2 8704    // 32*136*2
#define STG2 37888
// gemm1 smem: 3 stages + a_s(512) + c_s(512) + pm4(2048) + ps4(2048)
#define G1_AS (3 * STG1)
#define G1_CS (G1_AS + 512)
#define G1_PM (G1_AS + 1024)
#define G1_PS (G1_PM + 2048)
#define SMB1 (G1_PS + 2048)
// gemm2 smem: 3 stages + cm(1024) + ci(1024) + h(512)
#define G2_CM (3 * STG2)
#define G2_CI (G2_CM + 1024)
#define G2_HS (G2_CI + 1024)
#define SMB2 (G2_HS + 512)

typedef wmma::fragment<wmma::accumulator, 16, 16, 16, float> AccFrag;
typedef wmma::fragment<wmma::matrix_a, 16, 16, 16, __nv_bfloat16, wmma::row_major> AFrag;
typedef wmma::fragment<wmma::matrix_b, 16, 16, 16, __nv_bfloat16, wmma::col_major> BFragC;
typedef wmma::fragment<wmma::matrix_b, 16, 16, 16, __nv_bfloat16, wmma::row_major> BFragR;

// one K=32 chunk, gemm1 flavor (B col-major [n][k])
__device__ __forceinline__ void chunk_g1(const char* smc, int bo, int wm, int wn,
                                         AccFrag acc[2][2]) {
    const __nv_bfloat16* Ah = (const __nv_bfloat16*)(smc + bo);
    const __nv_bfloat16* Al = (const __nv_bfloat16*)(smc + bo + MATB1);
    const __nv_bfloat16* Bh = (const __nv_bfloat16*)(smc + bo + 2 * MATB1);
    const __nv_bfloat16* Bl = (const __nv_bfloat16*)(smc + bo + 3 * MATB1);
#pragma unroll
    for (int k0 = 0; k0 < 32; k0 += 16) {
        AFrag ah[2];
        BFragC bh[2];
#pragma unroll
        for (int i = 0; i < 2; i++)
            wmma::load_matrix_sync(ah[i], Ah + (wm * 32 + i * 16) * LDSA + k0, LDSA);
#pragma unroll
        for (int j = 0; j < 2; j++)
            wmma::load_matrix_sync(bh[j], Bh + (wn * 32 + j * 16) * LDSA + k0, LDSA);
#pragma unroll
        for (int i = 0; i < 2; i++)
#pragma unroll
            for (int j = 0; j < 2; j++) wmma::mma_sync(acc[i][j], ah[i], bh[j], acc[i][j]);
        BFragC bl[2];
#pragma unroll
        for (int j = 0; j < 2; j++)
            wmma::load_matrix_sync(bl[j], Bl + (wn * 32 + j * 16) * LDSA + k0, LDSA);
#pragma unroll
        for (int i = 0; i < 2; i++)
#pragma unroll
            for (int j = 0; j < 2; j++) wmma::mma_sync(acc[i][j], ah[i], bl[j], acc[i][j]);
        AFrag al[2];
#pragma unroll
        for (int i = 0; i < 2; i++)
            wmma::load_matrix_sync(al[i], Al + (wm * 32 + i * 16) * LDSA + k0, LDSA);
#pragma unroll
        for (int i = 0; i < 2; i++)
#pragma unroll
            for (int j = 0; j < 2; j++) wmma::mma_sync(acc[i][j], al[i], bh[j], acc[i][j]);
    }
}

// one K=32 chunk, gemm2 flavor (B row-major [k][n])
__device__ __forceinline__ void chunk_g2(const char* smc, int bo, int wm, int wn,
                                         AccFrag acc[2][2]) {
    const __nv_bfloat16* Ah = (const __nv_bfloat16*)(smc + bo);
    const __nv_bfloat16* Al = (const __nv_bfloat16*)(smc + bo + MATB1);
    const __nv_bfloat16* Bh = (const __nv_bfloat16*)(smc + bo + 2 * MATB1);
    const __nv_bfloat16* Bl = (const __nv_bfloat16*)(smc + bo + 2 * MATB1 + MATB2);
#pragma unroll
    for (int k0 = 0; k0 < 32; k0 += 16) {
        AFrag ah[2];
        BFragR bh[2];
#pragma unroll
        for (int i = 0; i < 2; i++)
            wmma::load_matrix_sync(ah[i], Ah + (wm * 32 + i * 16) * LDSA + k0, LDSA);
#pragma unroll
        for (int j = 0; j < 2; j++)
            wmma::load_matrix_sync(bh[j], Bh + k0 * LDSB2 + wn * 32 + j * 16, LDSB2);
#pragma unroll
        for (int i = 0; i < 2; i++)
#pragma unroll
            for (int j = 0; j < 2; j++) wmma::mma_sync(acc[i][j], ah[i], bh[j], acc[i][j]);
        BFragR bl[2];
#pragma unroll
        for (int j = 0; j < 2; j++)
            wmma::load_matrix_sync(bl[j], Bl + k0 * LDSB2 + wn * 32 + j * 16, LDSB2);
#pragma unroll
        for (int i = 0; i < 2; i++)
#pragma unroll
            for (int j = 0; j < 2; j++) wmma::mma_sync(acc[i][j], ah[i], bl[j], acc[i][j]);
        AFrag al[2];
#pragma unroll
        for (int i = 0; i < 2; i++)
            wmma::load_matrix_sync(al[i], Al + (wm * 32 + i * 16) * LDSA + k0, LDSA);
#pragma unroll
        for (int i = 0; i < 2; i++)
#pragma unroll
            for (int j = 0; j < 2; j++) wmma::mma_sync(acc[i][j], al[i], bh[j], acc[i][j]);
    }
}

// ---------------------------------------------------------------------------
// K1: split(ctx*w3)->Ahi/Alo + a=ctx.w1 ; split(q)->Bhi/Blo + c=q.w2
// ---------------------------------------------------------------------------
__global__ void convert_kernel(const float* __restrict__ ctx,
                               const float* __restrict__ qry,
                               const float* __restrict__ w) {
    int gw = (blockIdx.x * blockDim.x + threadIdx.x) >> 5;
    int lane = threadIdx.x & 31;
    if (gw < BB * TT) {
        const float* row = ctx + (size_t)gw * DD;
        float acc = 0.f;
#pragma unroll
        for (int i = 0; i < 4; i++) {
            int col = i * 128 + lane * 4;
            float4 x = *(const float4*)(row + col);
            float4 w1v = *(const float4*)(w + col);
            acc += x.x * w1v.x + x.y * w1v.y + x.z * w1v.z + x.w * w1v.w;
            float4 w3v = *(const float4*)(w + 2 * DD + col);
            uint2 hi, lo;
            split4(x.x * w3v.x, x.y * w3v.y, x.z * w3v.z, x.w * w3v.w, hi, lo);
            size_t o = (size_t)gw * DD + col;
            *(uint2*)((char*)g_Ahi + o * 2) = hi;
            *(uint2*)((char*)g_Alo + o * 2) = lo;
        }
#pragma unroll
        for (int o = 16; o; o >>= 1) acc += __shfl_xor_sync(~0u, acc, o);
        if (lane == 0) {
            g_a[gw] = acc;
            g_rmu[gw] = 0u;
        }
    } else {
        int r = gw - BB * TT;
        if (r >= BB * JJ) return;
        const float* row = qry + (size_t)r * DD;
        float acc = 0.f;
#pragma unroll
        for (int i = 0; i < 4; i++) {
            int col = i * 128 + lane * 4;
            float4 x = *(const float4*)(row + col);
            float4 w2v = *(const float4*)(w + DD + col);
            acc += x.x * w2v.x + x.y * w2v.y + x.z * w2v.z + x.w * w2v.w;
            uint2 hi, lo;
            split4(x.x, x.y, x.z, x.w, hi, lo);
            size_t o = (size_t)r * DD + col;
            *(uint2*)((char*)g_Bhi + o * 2) = hi;
            *(uint2*)((char*)g_Blo + o * 2) = lo;
        }
#pragma unroll
        for (int o = 16; o; o >>= 1) acc += __shfl_xor_sync(~0u, acc, o);
        if (lane == 0) g_c[r] = acc;
    }
}

// ---------------------------------------------------------------------------
// K2: GEMM1 (WMMA, 512 thr, 3-stage): S tile = (ctx*w3)@q^T + a + c
//     fused rowmax (atomicMax) + fused column softmax partials
// ---------------------------------------------------------------------------
__global__ __launch_bounds__(512) void gemm1_wmma() {
    extern __shared__ __align__(16) char smc[];
    int tid = threadIdx.x;
    int wid = tid >> 5, wm = wid >> 2, wn = wid & 3;
    int b = blockIdx.z, mt = blockIdx.y, m0 = mt * 128, n0 = blockIdx.x * 128;

    float* a_s = (float*)(smc + G1_AS);
    float* c_s = (float*)(smc + G1_CS);
    if (tid < 128) {
        a_s[tid] = g_a[b * TT + m0 + tid];
        c_s[tid] = g_c[b * JJ + n0 + tid];
    }

    const __nv_bfloat16* Ah = g_Ahi + (size_t)(b * TT + m0) * DD;
    const __nv_bfloat16* Al = g_Alo + (size_t)(b * TT + m0) * DD;
    const __nv_bfloat16* Bh = g_Bhi + (size_t)(b * JJ + n0) * DD;
    const __nv_bfloat16* Bl = g_Blo + (size_t)(b * JJ + n0) * DD;
    uint32_t sm0 = smem_u32(smc);

    AccFrag acc[2][2];
#pragma unroll
    for (int i = 0; i < 2; i++)
#pragma unroll
        for (int j = 0; j < 2; j++) wmma::fill_fragment(acc[i][j], 0.f);

    auto load_stage = [&](int stg, int kc) {
#pragma unroll 1
        for (int i = tid; i < 1024; i += 512) {
            int which = i >> 9, idx = i & 511;
            int row = idx >> 2, seg = idx & 3;
            const __nv_bfloat16* src = (which ? Al : Ah) + (size_t)row * DD + kc + seg * 8;
            cpa16(sm0 + stg + which * MATB1 + row * 80 + seg * 16, src);
        }
#pragma unroll 1
        for (int i = tid; i < 1024; i += 512) {
            int which = i >> 9, idx = i & 511;
            int row = idx >> 2, seg = idx & 3;
            const __nv_bfloat16* src = (which ? Bl : Bh) + (size_t)row * DD + kc + seg * 8;
            cpa16(sm0 + stg + 2 * MATB1 + which * MATB1 + row * 80 + seg * 16, src);
        }
        cpa_commit();
    };

    load_stage(0, 0);
    load_stage(STG1, 32);
    for (int c = 0; c < 16; c++) {
        int cb = (c % 3) * STG1;
        if (c + 2 < 16) {
            load_stage(((c + 2) % 3) * STG1, (c + 2) * 32);
            cpa_wait<2>();
        } else if (c + 1 < 16) {
            cpa_wait<1>();
        } else {
            cpa_wait<0>();
        }
        __syncthreads();
        chunk_g1(smc, cb, wm, wn, acc);
        __syncthreads();
    }

    // epilogue: stage to smem, bias, coalesced write + fused rowmax
    float* Su = (float*)smc;
#pragma unroll
    for (int i = 0; i < 2; i++)
#pragma unroll
        for (int j = 0; j < 2; j++)
            wmma::store_matrix_sync(Su + (wm * 32 + i * 16) * 132 + wn * 32 + j * 16,
                                    acc[i][j], 132, wmma::mem_row_major);
    __syncthreads();
    int col4 = (tid & 31) * 4, wr = tid >> 5;
    float* Sg = g_S + (size_t)(b * TT + m0) * JJ + n0;
#pragma unroll 1
    for (int r0 = 0; r0 < 128; r0 += 16) {
        int row = r0 + wr;
        float4 v = *(float4*)&Su[row * 132 + col4];
        float av = a_s[row];
        float4 cv = *(float4*)&c_s[col4];
        v.x += av + cv.x; v.y += av + cv.y; v.z += av + cv.z; v.w += av + cv.w;
        *(float4*)(Sg + (size_t)row * JJ + col4) = v;
        float rm = fmaxf(fmaxf(v.x, v.y), fmaxf(v.z, v.w));
#pragma unroll
        for (int o = 16; o; o >>= 1) rm = fmaxf(rm, __shfl_xor_sync(~0u, rm, o));
        if ((tid & 31) == 0) atomicMax(&g_rmu[b * TT + m0 + row], enc_f(rm));
    }

    // fused column softmax partials: 4 groups x 128 cols, online max/sum
    float* pm4 = (float*)(smc + G1_PM);
    float* ps4 = (float*)(smc + G1_PS);
    int col = tid & 127, grp = tid >> 7;
    float m = -3.0e38f, s = 0.f;
    float cval = c_s[col];
#pragma unroll 1
    for (int r = grp * 32; r < grp * 32 + 32; r++) {
        float v = Su[r * 132 + col] + a_s[r] + cval;
        if (v > m) { s = s * __expf(m - v) + 1.f; m = v; }
        else s += __expf(v - m);
    }
    pm4[grp * 128 + col] = m;
    ps4[grp * 128 + col] = s;
    __syncthreads();
    if (tid < 128) {
        float M = pm4[tid];
#pragma unroll
        for (int g = 1; g < 4; g++) M = fmaxf(M, pm4[g * 128 + tid]);
        float S = 0.f;
#pragma unroll
        for (int g = 0; g < 4; g++)
            S += ps4[g * 128 + tid] * __expf(pm4[g * 128 + tid] - M);
        g_pm[(b * 8 + mt) * JJ + n0 + tid] = M;
        g_ps[(b * 8 + mt) * JJ + n0 + tid] = S;
    }
}

// ---------------------------------------------------------------------------
// K3: b_t = softmax_t(rowmax); h[b,d] = sum_t b_t * ctx
// ---------------------------------------------------------------------------
__global__ __launch_bounds__(128) void bth_kernel(const float* __restrict__ ctx) {
    int b = blockIdx.y, q = blockIdx.x, tid = threadIdx.x;
    int wid = tid >> 5, lane = tid & 31;
    __shared__ float e_s[TT];
    __shared__ float red_m[4], red_s[4];
    float v[8];
    float m = -3.0e38f;
#pragma unroll
    for (int i = 0; i < 8; i++) {
        v[i] = dec_f(g_rmu[b * TT + tid + i * 128]);
        m = fmaxf(m, v[i]);
    }
#pragma unroll
    for (int o = 16; o; o >>= 1) m = fmaxf(m, __shfl_xor_sync(~0u, m, o));
    if (lane == 0) red_m[wid] = m;
    __syncthreads();
    m = fmaxf(fmaxf(red_m[0], red_m[1]), fmaxf(red_m[2], red_m[3]));
    float s = 0.f;
#pragma unroll
    for (int i = 0; i < 8; i++) {
        float e = __expf(v[i] - m);
        e_s[tid + i * 128] = e;
        s += e;
    }
#pragma unroll
    for (int o = 16; o; o >>= 1) s += __shfl_xor_sync(~0u, s, o);
    if (lane == 0) red_s[wid] = s;
    __syncthreads();
    float inv = 1.f / (red_s[0] + red_s[1] + red_s[2] + red_s[3]);
    int d = q * 128 + tid;
    const float* cb = ctx + (size_t)b * TT * DD + d;
    float a0 = 0.f, a1 = 0.f, a2 = 0.f, a3 = 0.f;
    for (int t = 0; t < TT; t += 4) {
        a0 += e_s[t + 0] * cb[(size_t)(t + 0) * DD];
        a1 += e_s[t + 1] * cb[(size_t)(t + 1) * DD];
        a2 += e_s[t + 2] * cb[(size_t)(t + 2) * DD];
        a3 += e_s[t + 3] * cb[(size_t)(t + 3) * DD];
    }
    g_h[b * DD + d] = (a0 + a1 + a2 + a3) * inv;
}

// ---------------------------------------------------------------------------
// K4: GEMM2 (WMMA, 512 thr, 3-stage): U = softmax_col(S) @ q
//     colstats combine in prologue; fused G epilogue
// ---------------------------------------------------------------------------
__global__ __launch_bounds__(512) void gemm2_wmma(const float* __restrict__ ctx,
                                                  float* __restrict__ out) {
    extern __shared__ __align__(16) char smc[];
    int tid = threadIdx.x;
    int wid = tid >> 5, wm = wid >> 2, wn = wid & 3;
    int b = blockIdx.z, m0 = blockIdx.y * 128, n0 = blockIdx.x * 128;

    float* cm_s = (float*)(smc + G2_CM);
    float* ci_s = (float*)(smc + G2_CI);
    float* h_s = (float*)(smc + G2_HS);
    if (tid < 256) {
        float M = -3.0e38f;
#pragma unroll
        for (int p = 0; p < 8; p++) M = fmaxf(M, g_pm[(b * 8 + p) * JJ + tid]);
        float S = 0.f;
#pragma unroll
        for (int p = 0; p < 8; p++)
            S += g_ps[(b * 8 + p) * JJ + tid] * __expf(g_pm[(b * 8 + p) * JJ + tid] - M);
        cm_s[tid] = M;
        ci_s[tid] = 1.f / S;
    } else if (tid < 384) {
        h_s[tid - 256] = g_h[b * DD + n0 + tid - 256];
    }
    __syncthreads();

    const float* Sg = g_S + (size_t)(b * TT + m0) * JJ;
    const __nv_bfloat16* Bh = g_Bhi + (size_t)b * JJ * DD + n0;
    const __nv_bfloat16* Bl = g_Blo + (size_t)b * JJ * DD + n0;
    uint32_t sm0 = smem_u32(smc);

    AccFrag acc[2][2];
#pragma unroll
    for (int i = 0; i < 2; i++)
#pragma unroll
        for (int j = 0; j < 2; j++) wmma::fill_fragment(acc[i][j], 0.f);

    auto load_stage = [&](int stg, int kc) {
#pragma unroll 1
        for (int i = tid; i < 1024; i += 512) {
            int which = i >> 9, idx = i & 511;
            int row = idx >> 4, seg = idx & 15;
            const __nv_bfloat16* src =
                (which ? Bl : Bh) + (size_t)(kc + row) * DD + seg * 8;
            cpa16(sm0 + stg + 2 * MATB1 + which * MATB2 + row * 272 + seg * 16, src);
        }
        cpa_commit();
#pragma unroll 1
        for (int i = tid; i < 1024; i += 512) {
            int row = i >> 3, c4 = (i & 7) * 4;
            int jb = kc + c4;
            float4 v = *(const float4*)(Sg + (size_t)row * JJ + jb);
            float p0 = __expf(v.x - cm_s[jb + 0]) * ci_s[jb + 0];
            float p1 = __expf(v.y - cm_s[jb + 1]) * ci_s[jb + 1];
            float p2 = __expf(v.z - cm_s[jb + 2]) * ci_s[jb + 2];
            float p3 = __expf(v.w - cm_s[jb + 3]) * ci_s[jb + 3];
            uint2 hi, lo;
            split4(p0, p1, p2, p3, hi, lo);
            *(uint2*)(smc + stg + row * 80 + c4 * 2) = hi;
            *(uint2*)(smc + stg + MATB1 + row * 80 + c4 * 2) = lo;
        }
    };

    load_stage(0, 0);
    load_stage(STG2, 32);
    for (int c = 0; c < 8; c++) {
        int cb = (c % 3) * STG2;
        if (c + 2 < 8) {
            load_stage(((c + 2) % 3) * STG2, (c + 2) * 32);
            cpa_wait<2>();
        } else if (c + 1 < 8) {
            cpa_wait<1>();
        } else {
            cpa_wait<0>();
        }
        __syncthreads();
        chunk_g2(smc, cb, wm, wn, acc);
        __syncthreads();
    }

    // epilogue: stage U, fused G = [ctx, U, ctx*U, ctx*h]
    float* Su = (float*)smc;
#pragma unroll
    for (int i = 0; i < 2; i++)
#pragma unroll
        for (int j = 0; j < 2; j++)
            wmma::store_matrix_sync(Su + (wm * 32 + i * 16) * 132 + wn * 32 + j * 16,
                                    acc[i][j], 132, wmma::mem_row_major);
    __syncthreads();
    int col4 = (tid & 31) * 4, wr = tid >> 5;
#pragma unroll 1
    for (int r0 = 0; r0 < 128; r0 += 16) {
        int row = r0 + wr;
        float4 u = *(float4*)&Su[row * 132 + col4];
        float4 cx = *(const float4*)(ctx + (size_t)(b * TT + m0 + row) * DD + n0 + col4);
        float4 h4 = *(float4*)&h_s[col4];
        float* og = out + (size_t)(b * TT + m0 + row) * 2048 + n0 + col4;
        float4 cu, ch;
        cu.x = cx.x * u.x; cu.y = cx.y * u.y; cu.z = cx.z * u.z; cu.w = cx.w * u.w;
        ch.x = cx.x * h4.x; ch.y = cx.y * h4.y; ch.z = cx.z * h4.z; ch.w = cx.w * h4.w;
        *(float4*)(og) = cx;
        *(float4*)(og + 512) = u;
        *(float4*)(og + 1024) = cu;
        *(float4*)(og + 1536) = ch;
    }
}

// ---------------------------------------------------------------------------
extern "C" void kernel_launch(void* const* d_in, const int* in_sizes, int n_in,
                              void* d_out, int out_size) {
    const float* ctx = (const float*)d_in[0];
    const float* qry = (const float*)d_in[1];
    const float* w = (const float*)d_in[2];
    float* out = (float*)d_out;

    cudaFuncSetAttribute(gemm1_wmma, cudaFuncAttributeMaxDynamicSharedMemorySize, SMB1);
    cudaFuncSetAttribute(gemm2_wmma, cudaFuncAttributeMaxDynamicSharedMemorySize, SMB2);

    convert_kernel<<<(BB * TT + BB * JJ) / 8, 256>>>(ctx, qry, w);
    gemm1_wmma<<<dim3(JJ / 128, TT / 128, BB), 512, SMB1>>>();
    bth_kernel<<<dim3(4, BB), 128>>>(ctx);
    gemm2_wmma<<<dim3(DD / 128, TT / 128, BB), 512, SMB2>>>(ctx, out);
}

// round 10
// speedup vs baseline: 1.7085x; 1.0955x over previous
#include <cuda_runtime.h>
#include <cuda_bf16.h>
#include <mma.h>
#include <stdint.h>
#include <math.h>

using namespace nvcuda;

#define BB 32
#define TT 1024
#define JJ 256
#define DD 512

// ------------------- device scratch (no runtime alloc) ----------------------
__device__ float g_S[(size_t)BB * TT * JJ];
__device__ __nv_bfloat16 g_Ahi[(size_t)BB * TT * DD];  // split(ctx*w3)
__device__ __nv_bfloat16 g_Alo[(size_t)BB * TT * DD];
__device__ __nv_bfloat16 g_Bhi[(size_t)BB * JJ * DD];  // split(q) [b,j,d]
__device__ __nv_bfloat16 g_Blo[(size_t)BB * JJ * DD];
__device__ float g_a[BB * TT], g_c[BB * JJ];
__device__ float g_rm[BB * TT];
__device__ float g_h[BB * DD];
__device__ float g_pm[BB * 8 * JJ], g_ps[BB * 8 * JJ];

// ------------------------------ helpers -------------------------------------
__device__ __forceinline__ uint32_t smem_u32(const void* p) {
    uint32_t a;
    asm("{ .reg .u64 t; cvta.to.shared.u64 t, %1; cvt.u32.u64 %0, t; }"
        : "=r"(a) : "l"(p));
    return a;
}
__device__ __forceinline__ void cpa16(uint32_t d, const void* s) {
    asm volatile("cp.async.cg.shared.global [%0], [%1], 16;" :: "r"(d), "l"(s));
}
__device__ __forceinline__ void cpa_commit() {
    asm volatile("cp.async.commit_group;" ::: "memory");
}
template <int N>
__device__ __forceinline__ void cpa_wait() {
    asm volatile("cp.async.wait_group %0;" :: "n"(N) : "memory");
}

__device__ __forceinline__ void split4(float x0, float x1, float x2, float x3,
                                       uint2& hi, uint2& lo) {
    __nv_bfloat16 h0 = __float2bfloat16(x0), h1 = __float2bfloat16(x1);
    __nv_bfloat16 h2 = __float2bfloat16(x2), h3 = __float2bfloat16(x3);
    __nv_bfloat16 l0 = __float2bfloat16(x0 - __bfloat162float(h0));
    __nv_bfloat16 l1 = __float2bfloat16(x1 - __bfloat162float(h1));
    __nv_bfloat16 l2 = __float2bfloat16(x2 - __bfloat162float(h2));
    __nv_bfloat16 l3 = __float2bfloat16(x3 - __bfloat162float(h3));
    hi.x = ((uint32_t)__bfloat16_as_ushort(h1) << 16) | __bfloat16_as_ushort(h0);
    hi.y = ((uint32_t)__bfloat16_as_ushort(h3) << 16) | __bfloat16_as_ushort(h2);
    lo.x = ((uint32_t)__bfloat16_as_ushort(l1) << 16) | __bfloat16_as_ushort(l0);
    lo.y = ((uint32_t)__bfloat16_as_ushort(l3) << 16) | __bfloat16_as_ushort(l2);
}

// ------------------------- layout constants ---------------------------------
#define LDSA 40        // 32 k + 8 pad (80B rows)
#define MATA 10240     // 128*40*2 (A matrix, both gemms)
// gemm1: B = 256 rows x 40 elems (k-major)
#define MATB1 20480
#define STG1 61440     // Ahi,Alo(2*10240) + Bhi,Blo(2*20480)
#define G1_AS (3 * STG1)
#define G1_CS (G1_AS + 512)
#define G1_PM (G1_CS + 1024)
#define G1_PS (G1_PM + 2048)
#define SMB1 (G1_PS + 2048)
// gemm2: B = 32 rows x 264 elems (n-major)
#define LDSB2 264
#define MATB2 16896
#define STG2 54272     // 2*10240 + 2*16896
#define G2_CM (3 * STG2)
#define G2_CI (G2_CM + 1024)
#define G2_HS (G2_CI + 1024)
#define SMB2 (G2_HS + 1024)

typedef wmma::fragment<wmma::accumulator, 16, 16, 16, float> AccFrag;
typedef wmma::fragment<wmma::matrix_a, 16, 16, 16, __nv_bfloat16, wmma::row_major> AFrag;
typedef wmma::fragment<wmma::matrix_b, 16, 16, 16, __nv_bfloat16, wmma::col_major> BFragC;
typedef wmma::fragment<wmma::matrix_b, 16, 16, 16, __nv_bfloat16, wmma::row_major> BFragR;

// one K=32 chunk, gemm1 flavor (B col-major [n][k]); warp tile 32x64
__device__ __forceinline__ void chunk_g1(const char* smc, int bo, int wm, int wn,
                                         AccFrag acc[2][4]) {
    const __nv_bfloat16* Ah = (const __nv_bfloat16*)(smc + bo);
    const __nv_bfloat16* Al = (const __nv_bfloat16*)(smc + bo + MATA);
    const __nv_bfloat16* Bh = (const __nv_bfloat16*)(smc + bo + 2 * MATA);
    const __nv_bfloat16* Bl = (const __nv_bfloat16*)(smc + bo + 2 * MATA + MATB1);
#pragma unroll
    for (int k0 = 0; k0 < 32; k0 += 16) {
        AFrag ah[2], al[2];
#pragma unroll
        for (int i = 0; i < 2; i++) {
            wmma::load_matrix_sync(ah[i], Ah + (wm * 32 + i * 16) * LDSA + k0, LDSA);
            wmma::load_matrix_sync(al[i], Al + (wm * 32 + i * 16) * LDSA + k0, LDSA);
        }
#pragma unroll
        for (int jh = 0; jh < 2; jh++) {
            BFragC bh[2], bl[2];
#pragma unroll
            for (int j = 0; j < 2; j++)
                wmma::load_matrix_sync(bh[j], Bh + (wn * 64 + jh * 32 + j * 16) * LDSA + k0, LDSA);
#pragma unroll
            for (int i = 0; i < 2; i++)
#pragma unroll
                for (int j = 0; j < 2; j++)
                    wmma::mma_sync(acc[i][jh * 2 + j], ah[i], bh[j], acc[i][jh * 2 + j]);
#pragma unroll
            for (int j = 0; j < 2; j++)
                wmma::load_matrix_sync(bl[j], Bl + (wn * 64 + jh * 32 + j * 16) * LDSA + k0, LDSA);
#pragma unroll
            for (int i = 0; i < 2; i++)
#pragma unroll
                for (int j = 0; j < 2; j++)
                    wmma::mma_sync(acc[i][jh * 2 + j], ah[i], bl[j], acc[i][jh * 2 + j]);
#pragma unroll
            for (int i = 0; i < 2; i++)
#pragma unroll
                for (int j = 0; j < 2; j++)
                    wmma::mma_sync(acc[i][jh * 2 + j], al[i], bh[j], acc[i][jh * 2 + j]);
        }
    }
}

// one K=32 chunk, gemm2 flavor (B row-major [k][n]); warp tile 32x64
__device__ __forceinline__ void chunk_g2(const char* smc, int bo, int wm, int wn,
                                         AccFrag acc[2][4]) {
    const __nv_bfloat16* Ah = (const __nv_bfloat16*)(smc + bo);
    const __nv_bfloat16* Al = (const __nv_bfloat16*)(smc + bo + MATA);
    const __nv_bfloat16* Bh = (const __nv_bfloat16*)(smc + bo + 2 * MATA);
    const __nv_bfloat16* Bl = (const __nv_bfloat16*)(smc + bo + 2 * MATA + MATB2);
#pragma unroll
    for (int k0 = 0; k0 < 32; k0 += 16) {
        AFrag ah[2], al[2];
#pragma unroll
        for (int i = 0; i < 2; i++) {
            wmma::load_matrix_sync(ah[i], Ah + (wm * 32 + i * 16) * LDSA + k0, LDSA);
            wmma::load_matrix_sync(al[i], Al + (wm * 32 + i * 16) * LDSA + k0, LDSA);
        }
#pragma unroll
        for (int jh = 0; jh < 2; jh++) {
            BFragR bh[2], bl[2];
#pragma unroll
            for (int j = 0; j < 2; j++)
                wmma::load_matrix_sync(bh[j], Bh + k0 * LDSB2 + wn * 64 + jh * 32 + j * 16, LDSB2);
#pragma unroll
            for (int i = 0; i < 2; i++)
#pragma unroll
                for (int j = 0; j < 2; j++)
                    wmma::mma_sync(acc[i][jh * 2 + j], ah[i], bh[j], acc[i][jh * 2 + j]);
#pragma unroll
            for (int j = 0; j < 2; j++)
                wmma::load_matrix_sync(bl[j], Bl + k0 * LDSB2 + wn * 64 + jh * 32 + j * 16, LDSB2);
#pragma unroll
            for (int i = 0; i < 2; i++)
#pragma unroll
                for (int j = 0; j < 2; j++)
                    wmma::mma_sync(acc[i][jh * 2 + j], ah[i], bl[j], acc[i][jh * 2 + j]);
#pragma unroll
            for (int i = 0; i < 2; i++)
#pragma unroll
                for (int j = 0; j < 2; j++)
                    wmma::mma_sync(acc[i][jh * 2 + j], al[i], bh[j], acc[i][jh * 2 + j]);
        }
    }
}

// ---------------------------------------------------------------------------
// K1: split(ctx*w3)->Ahi/Alo + a=ctx.w1 ; split(q)->Bhi/Blo + c=q.w2
// ---------------------------------------------------------------------------
__global__ void convert_kernel(const float* __restrict__ ctx,
                               const float* __restrict__ qry,
                               const float* __restrict__ w) {
    int gw = (blockIdx.x * blockDim.x + threadIdx.x) >> 5;
    int lane = threadIdx.x & 31;
    if (gw < BB * TT) {
        const float* row = ctx + (size_t)gw * DD;
        float acc = 0.f;
#pragma unroll
        for (int i = 0; i < 4; i++) {
            int col = i * 128 + lane * 4;
            float4 x = *(const float4*)(row + col);
            float4 w1v = *(const float4*)(w + col);
            acc += x.x * w1v.x + x.y * w1v.y + x.z * w1v.z + x.w * w1v.w;
            float4 w3v = *(const float4*)(w + 2 * DD + col);
            uint2 hi, lo;
            split4(x.x * w3v.x, x.y * w3v.y, x.z * w3v.z, x.w * w3v.w, hi, lo);
            size_t o = (size_t)gw * DD + col;
            *(uint2*)((char*)g_Ahi + o * 2) = hi;
            *(uint2*)((char*)g_Alo + o * 2) = lo;
        }
#pragma unroll
        for (int o = 16; o; o >>= 1) acc += __shfl_xor_sync(~0u, acc, o);
        if (lane == 0) g_a[gw] = acc;
    } else {
        int r = gw - BB * TT;
        if (r >= BB * JJ) return;
        const float* row = qry + (size_t)r * DD;
        float acc = 0.f;
#pragma unroll
        for (int i = 0; i < 4; i++) {
            int col = i * 128 + lane * 4;
            float4 x = *(const float4*)(row + col);
            float4 w2v = *(const float4*)(w + DD + col);
            acc += x.x * w2v.x + x.y * w2v.y + x.z * w2v.z + x.w * w2v.w;
            uint2 hi, lo;
            split4(x.x, x.y, x.z, x.w, hi, lo);
            size_t o = (size_t)r * DD + col;
            *(uint2*)((char*)g_Bhi + o * 2) = hi;
            *(uint2*)((char*)g_Blo + o * 2) = lo;
        }
#pragma unroll
        for (int o = 16; o; o >>= 1) acc += __shfl_xor_sync(~0u, acc, o);
        if (lane == 0) g_c[r] = acc;
    }
}

// ---------------------------------------------------------------------------
// K2: GEMM1 (WMMA, 512 thr, 3-stage): S[b, m0:+128, 0:256] (full J per CTA)
//     fused rowmax (direct store) + fused column softmax partials
// ---------------------------------------------------------------------------
__global__ __launch_bounds__(512) void gemm1_wmma() {
    extern __shared__ __align__(16) char smc[];
    int tid = threadIdx.x;
    int wid = tid >> 5, wm = wid >> 2, wn = wid & 3;
    int lane = tid & 31;
    int b = blockIdx.y, mt = blockIdx.x, m0 = mt * 128;

    float* a_s = (float*)(smc + G1_AS);
    float* c_s = (float*)(smc + G1_CS);
    if (tid < 128) a_s[tid] = g_a[b * TT + m0 + tid];
    else if (tid < 384) c_s[tid - 128] = g_c[b * JJ + tid - 128];

    const __nv_bfloat16* Ah = g_Ahi + (size_t)(b * TT + m0) * DD;
    const __nv_bfloat16* Al = g_Alo + (size_t)(b * TT + m0) * DD;
    const __nv_bfloat16* Bh = g_Bhi + (size_t)b * JJ * DD;
    const __nv_bfloat16* Bl = g_Blo + (size_t)b * JJ * DD;
    uint32_t sm0 = smem_u32(smc);

    AccFrag acc[2][4];
#pragma unroll
    for (int i = 0; i < 2; i++)
#pragma unroll
        for (int j = 0; j < 4; j++) wmma::fill_fragment(acc[i][j], 0.f);

    auto load_stage = [&](int stg, int kc) {
#pragma unroll 1
        for (int i = tid; i < 1024; i += 512) {
            int which = i >> 9, idx = i & 511;
            int row = idx >> 2, seg = idx & 3;
            const __nv_bfloat16* src = (which ? Al : Ah) + (size_t)row * DD + kc + seg * 8;
            cpa16(sm0 + stg + which * MATA + row * 80 + seg * 16, src);
        }
#pragma unroll 1
        for (int i = tid; i < 2048; i += 512) {
            int which = i >> 10, idx = i & 1023;
            int row = idx >> 2, seg = idx & 3;
            const __nv_bfloat16* src = (which ? Bl : Bh) + (size_t)row * DD + kc + seg * 8;
            cpa16(sm0 + stg + 2 * MATA + which * MATB1 + row * 80 + seg * 16, src);
        }
        cpa_commit();
    };

    load_stage(0, 0);
    load_stage(STG1, 32);
    for (int c = 0; c < 16; c++) {
        int cb = (c % 3) * STG1;
        if (c + 2 < 16) {
            load_stage(((c + 2) % 3) * STG1, (c + 2) * 32);
            cpa_wait<2>();
        } else if (c + 1 < 16) {
            cpa_wait<1>();
        } else {
            cpa_wait<0>();
        }
        __syncthreads();
        chunk_g1(smc, cb, wm, wn, acc);
        __syncthreads();
    }

    // epilogue: stage 128x256 to smem (ld 260), bias, coalesced write + rowmax
    float* Su = (float*)smc;
#pragma unroll
    for (int i = 0; i < 2; i++)
#pragma unroll
        for (int j = 0; j < 4; j++)
            wmma::store_matrix_sync(Su + (wm * 32 + i * 16) * 260 + wn * 64 + j * 16,
                                    acc[i][j], 260, wmma::mem_row_major);
    __syncthreads();
    float* Sg = g_S + (size_t)(b * TT + m0) * JJ;
    int c4a = lane * 4, c4b = 128 + lane * 4;
#pragma unroll 1
    for (int r0 = 0; r0 < 128; r0 += 16) {
        int row = r0 + wid;
        float av = a_s[row];
        float4 v1 = *(float4*)&Su[row * 260 + c4a];
        float4 cv1 = *(float4*)&c_s[c4a];
        v1.x += av + cv1.x; v1.y += av + cv1.y; v1.z += av + cv1.z; v1.w += av + cv1.w;
        float4 v2 = *(float4*)&Su[row * 260 + c4b];
        float4 cv2 = *(float4*)&c_s[c4b];
        v2.x += av + cv2.x; v2.y += av + cv2.y; v2.z += av + cv2.z; v2.w += av + cv2.w;
        *(float4*)(Sg + (size_t)row * JJ + c4a) = v1;
        *(float4*)(Sg + (size_t)row * JJ + c4b) = v2;
        float rm = fmaxf(fmaxf(fmaxf(v1.x, v1.y), fmaxf(v1.z, v1.w)),
                         fmaxf(fmaxf(v2.x, v2.y), fmaxf(v2.z, v2.w)));
#pragma unroll
        for (int o = 16; o; o >>= 1) rm = fmaxf(rm, __shfl_xor_sync(~0u, rm, o));
        if (lane == 0) g_rm[b * TT + m0 + row] = rm;
    }

    // fused column softmax partials: 2 groups of 64 rows x 256 cols
    float* pm2 = (float*)(smc + G1_PM);
    float* ps2 = (float*)(smc + G1_PS);
    int col = tid & 255, grp = tid >> 8;
    float m = -3.0e38f, s = 0.f;
    float cval = c_s[col];
#pragma unroll 1
    for (int r = grp * 64; r < grp * 64 + 64; r++) {
        float v = Su[r * 260 + col] + a_s[r] + cval;
        if (v > m) { s = s * __expf(m - v) + 1.f; m = v; }
        else s += __expf(v - m);
    }
    pm2[grp * 256 + col] = m;
    ps2[grp * 256 + col] = s;
    __syncthreads();
    if (tid < 256) {
        float m0v = pm2[tid], m1v = pm2[256 + tid];
        float M = fmaxf(m0v, m1v);
        float S = ps2[tid] * __expf(m0v - M) + ps2[256 + tid] * __expf(m1v - M);
        g_pm[(b * 8 + mt) * JJ + tid] = M;
        g_ps[(b * 8 + mt) * JJ + tid] = S;
    }
}

// ---------------------------------------------------------------------------
// K3: b_t = softmax_t(rowmax); h[b,d] = sum_t b_t * ctx
// ---------------------------------------------------------------------------
__global__ __launch_bounds__(128) void bth_kernel(const float* __restrict__ ctx) {
    int b = blockIdx.y, q = blockIdx.x, tid = threadIdx.x;
    int wid = tid >> 5, lane = tid & 31;
    __shared__ float e_s[TT];
    __shared__ float red_m[4], red_s[4];
    float v[8];
    float m = -3.0e38f;
#pragma unroll
    for (int i = 0; i < 8; i++) {
        v[i] = g_rm[b * TT + tid + i * 128];
        m = fmaxf(m, v[i]);
    }
#pragma unroll
    for (int o = 16; o; o >>= 1) m = fmaxf(m, __shfl_xor_sync(~0u, m, o));
    if (lane == 0) red_m[wid] = m;
    __syncthreads();
    m = fmaxf(fmaxf(red_m[0], red_m[1]), fmaxf(red_m[2], red_m[3]));
    float s = 0.f;
#pragma unroll
    for (int i = 0; i < 8; i++) {
        float e = __expf(v[i] - m);
        e_s[tid + i * 128] = e;
        s += e;
    }
#pragma unroll
    for (int o = 16; o; o >>= 1) s += __shfl_xor_sync(~0u, s, o);
    if (lane == 0) red_s[wid] = s;
    __syncthreads();
    float inv = 1.f / (red_s[0] + red_s[1] + red_s[2] + red_s[3]);
    int d = q * 128 + tid;
    const float* cb = ctx + (size_t)b * TT * DD + d;
    float a0 = 0.f, a1 = 0.f, a2 = 0.f, a3 = 0.f;
    for (int t = 0; t < TT; t += 4) {
        a0 += e_s[t + 0] * cb[(size_t)(t + 0) * DD];
        a1 += e_s[t + 1] * cb[(size_t)(t + 1) * DD];
        a2 += e_s[t + 2] * cb[(size_t)(t + 2) * DD];
        a3 += e_s[t + 3] * cb[(size_t)(t + 3) * DD];
    }
    g_h[b * DD + d] = (a0 + a1 + a2 + a3) * inv;
}

// ---------------------------------------------------------------------------
// K4: GEMM2 (WMMA, 512 thr, 3-stage): U tile 128x256 = softmax_col(S) @ q
//     colstats combine in prologue; fused G epilogue
// ---------------------------------------------------------------------------
__global__ __launch_bounds__(512) void gemm2_wmma(const float* __restrict__ ctx,
                                                  float* __restrict__ out) {
    extern __shared__ __align__(16) char smc[];
    int tid = threadIdx.x;
    int wid = tid >> 5, wm = wid >> 2, wn = wid & 3;
    int lane = tid & 31;
    int b = blockIdx.z, m0 = blockIdx.y * 128, n0 = blockIdx.x * 256;

    float* cm_s = (float*)(smc + G2_CM);
    float* ci_s = (float*)(smc + G2_CI);
    float* h_s = (float*)(smc + G2_HS);
    if (tid < 256) {
        float M = -3.0e38f;
#pragma unroll
        for (int p = 0; p < 8; p++) M = fmaxf(M, g_pm[(b * 8 + p) * JJ + tid]);
        float S = 0.f;
#pragma unroll
        for (int p = 0; p < 8; p++)
            S += g_ps[(b * 8 + p) * JJ + tid] * __expf(g_pm[(b * 8 + p) * JJ + tid] - M);
        cm_s[tid] = M;
        ci_s[tid] = 1.f / S;
    } else {
        h_s[tid - 256] = g_h[b * DD + n0 + tid - 256];
    }
    __syncthreads();

    const float* Sg = g_S + (size_t)(b * TT + m0) * JJ;
    const __nv_bfloat16* Bh = g_Bhi + (size_t)b * JJ * DD + n0;
    const __nv_bfloat16* Bl = g_Blo + (size_t)b * JJ * DD + n0;
    uint32_t sm0 = smem_u32(smc);

    AccFrag acc[2][4];
#pragma unroll
    for (int i = 0; i < 2; i++)
#pragma unroll
        for (int j = 0; j < 4; j++) wmma::fill_fragment(acc[i][j], 0.f);

    auto load_stage = [&](int stg, int kc) {
#pragma unroll 1
        for (int i = tid; i < 2048; i += 512) {
            int which = i >> 10, idx = i & 1023;
            int row = idx >> 5, seg = idx & 31;
            const __nv_bfloat16* src =
                (which ? Bl : Bh) + (size_t)(kc + row) * DD + seg * 8;
            cpa16(sm0 + stg + 2 * MATA + which * MATB2 + row * 528 + seg * 16, src);
        }
        cpa_commit();
#pragma unroll 1
        for (int i = tid; i < 1024; i += 512) {
            int row = i >> 3, c4 = (i & 7) * 4;
            int jb = kc + c4;
            float4 v = *(const float4*)(Sg + (size_t)row * JJ + jb);
            float p0 = __expf(v.x - cm_s[jb + 0]) * ci_s[jb + 0];
            float p1 = __expf(v.y - cm_s[jb + 1]) * ci_s[jb + 1];
            float p2 = __expf(v.z - cm_s[jb + 2]) * ci_s[jb + 2];
            float p3 = __expf(v.w - cm_s[jb + 3]) * ci_s[jb + 3];
            uint2 hi, lo;
            split4(p0, p1, p2, p3, hi, lo);
            *(uint2*)(smc + stg + row * 80 + c4 * 2) = hi;
            *(uint2*)(smc + stg + MATA + row * 80 + c4 * 2) = lo;
        }
    };

    load_stage(0, 0);
    load_stage(STG2, 32);
    for (int c = 0; c < 8; c++) {
        int cb = (c % 3) * STG2;
        if (c + 2 < 8) {
            load_stage(((c + 2) % 3) * STG2, (c + 2) * 32);
            cpa_wait<2>();
        } else if (c + 1 < 8) {
            cpa_wait<1>();
        } else {
            cpa_wait<0>();
        }
        __syncthreads();
        chunk_g2(smc, cb, wm, wn, acc);
        __syncthreads();
    }

    // epilogue: stage U (128x256, ld 260), fused G = [ctx, U, ctx*U, ctx*h]
    float* Su = (float*)smc;
#pragma unroll
    for (int i = 0; i < 2; i++)
#pragma unroll
        for (int j = 0; j < 4; j++)
            wmma::store_matrix_sync(Su + (wm * 32 + i * 16) * 260 + wn * 64 + j * 16,
                                    acc[i][j], 260, wmma::mem_row_major);
    __syncthreads();
    int c4a = lane * 4, c4b = 128 + lane * 4;
#pragma unroll 1
    for (int r0 = 0; r0 < 128; r0 += 16) {
        int row = r0 + wid;
        const float* crow = ctx + (size_t)(b * TT + m0 + row) * DD + n0;
        float* og = out + (size_t)(b * TT + m0 + row) * 2048 + n0;
#pragma unroll
        for (int half = 0; half < 2; half++) {
            int c4 = half ? c4b : c4a;
            float4 u = *(float4*)&Su[row * 260 + c4];
            float4 cx = *(const float4*)(crow + c4);
            float4 h4 = *(float4*)&h_s[c4];
            float4 cu, ch;
            cu.x = cx.x * u.x; cu.y = cx.y * u.y; cu.z = cx.z * u.z; cu.w = cx.w * u.w;
            ch.x = cx.x * h4.x; ch.y = cx.y * h4.y; ch.z = cx.z * h4.z; ch.w = cx.w * h4.w;
            *(float4*)(og + c4) = cx;
            *(float4*)(og + 512 + c4) = u;
            *(float4*)(og + 1024 + c4) = cu;
            *(float4*)(og + 1536 + c4) = ch;
        }
    }
}

// ---------------------------------------------------------------------------
extern "C" void kernel_launch(void* const* d_in, const int* in_sizes, int n_in,
                              void* d_out, int out_size) {
    const float* ctx = (const float*)d_in[0];
    const float* qry = (const float*)d_in[1];
    const float* w = (const float*)d_in[2];
    float* out = (float*)d_out;

    cudaFuncSetAttribute(gemm1_wmma, cudaFuncAttributeMaxDynamicSharedMemorySize, SMB1);
    cudaFuncSetAttribute(gemm2_wmma, cudaFuncAttributeMaxDynamicSharedMemorySize, SMB2);

    convert_kernel<<<(BB * TT + BB * JJ) / 8, 256>>>(ctx, qry, w);
    gemm1_wmma<<<dim3(TT / 128, BB), 512, SMB1>>>();
    bth_kernel<<<dim3(4, BB), 128>>>(ctx);
    gemm2_wmma<<<dim3(DD / 256, TT / 128, BB), 512, SMB2>>>(ctx, out);
}

// round 11
// speedup vs baseline: 1.9159x; 1.1214x over previous
#include <cuda_runtime.h>
#include <cuda_bf16.h>
#include <mma.h>
#include <stdint.h>
#include <math.h>

using namespace nvcuda;

#define BB 32
#define TT 1024
#define JJ 256
#define DD 512

// ------------------- device scratch (no runtime alloc) ----------------------
__device__ float g_S[(size_t)BB * TT * JJ];
__device__ __nv_bfloat16 g_Ahi[(size_t)BB * TT * DD];  // split(ctx*w3)
__device__ __nv_bfloat16 g_Alo[(size_t)BB * TT * DD];
__device__ __nv_bfloat16 g_Bhi[(size_t)BB * JJ * DD];  // split(q) [b,j,d]
__device__ __nv_bfloat16 g_Blo[(size_t)BB * JJ * DD];
__device__ float g_a[BB * TT], g_c[BB * JJ];
__device__ float g_rm[BB * TT];
__device__ float g_h[BB * DD];
__device__ float g_pm[BB * 16 * JJ], g_ps[BB * 16 * JJ];

// ------------------------------ helpers -------------------------------------
__device__ __forceinline__ uint32_t smem_u32(const void* p) {
    uint32_t a;
    asm("{ .reg .u64 t; cvta.to.shared.u64 t, %1; cvt.u32.u64 %0, t; }"
        : "=r"(a) : "l"(p));
    return a;
}
__device__ __forceinline__ void cpa16(uint32_t d, const void* s) {
    asm volatile("cp.async.cg.shared.global [%0], [%1], 16;" :: "r"(d), "l"(s));
}
__device__ __forceinline__ void cpa_commit() {
    asm volatile("cp.async.commit_group;" ::: "memory");
}
template <int N>
__device__ __forceinline__ void cpa_wait() {
    asm volatile("cp.async.wait_group %0;" :: "n"(N) : "memory");
}

__device__ __forceinline__ void split4(float x0, float x1, float x2, float x3,
                                       uint2& hi, uint2& lo) {
    __nv_bfloat16 h0 = __float2bfloat16(x0), h1 = __float2bfloat16(x1);
    __nv_bfloat16 h2 = __float2bfloat16(x2), h3 = __float2bfloat16(x3);
    __nv_bfloat16 l0 = __float2bfloat16(x0 - __bfloat162float(h0));
    __nv_bfloat16 l1 = __float2bfloat16(x1 - __bfloat162float(h1));
    __nv_bfloat16 l2 = __float2bfloat16(x2 - __bfloat162float(h2));
    __nv_bfloat16 l3 = __float2bfloat16(x3 - __bfloat162float(h3));
    hi.x = ((uint32_t)__bfloat16_as_ushort(h1) << 16) | __bfloat16_as_ushort(h0);
    hi.y = ((uint32_t)__bfloat16_as_ushort(h3) << 16) | __bfloat16_as_ushort(h2);
    lo.x = ((uint32_t)__bfloat16_as_ushort(l1) << 16) | __bfloat16_as_ushort(l0);
    lo.y = ((uint32_t)__bfloat16_as_ushort(l3) << 16) | __bfloat16_as_ushort(l2);
}

// ------------------------- layout constants ---------------------------------
#define LDSA 40        // 32 k + 8 pad (80B rows)
#define MATA 5120      // 64*40*2 (A matrix: 64 rows, both gemms)
// gemm1: B = 256 rows x 40 elems (k-major)
#define MATB1 20480
#define STG1 51200     // 2*5120 + 2*20480
#define G1_AS (2 * STG1)
#define G1_CS (G1_AS + 256)
#define SMB1 (G1_CS + 1024)
// gemm2: B = 32 rows x 264 elems (n-major)
#define LDSB2 264
#define MATB2 16896
#define STG2 44032     // 2*5120 + 2*16896
#define G2_CM (2 * STG2)
#define G2_CI (G2_CM + 1024)
#define G2_HS (G2_CI + 1024)
#define SMB2 (G2_HS + 1024)

typedef wmma::fragment<wmma::accumulator, 16, 16, 16, float> AccFrag;
typedef wmma::fragment<wmma::matrix_a, 16, 16, 16, __nv_bfloat16, wmma::row_major> AFrag;
typedef wmma::fragment<wmma::matrix_b, 16, 16, 16, __nv_bfloat16, wmma::col_major> BFragC;
typedef wmma::fragment<wmma::matrix_b, 16, 16, 16, __nv_bfloat16, wmma::row_major> BFragR;

// one K=32 chunk, gemm1 flavor (B col-major [n][k]); warp tile 32x64, warps 2x4
__device__ __forceinline__ void chunk_g1(const char* smc, int bo, int wm, int wn,
                                         AccFrag acc[2][4]) {
    const __nv_bfloat16* Ah = (const __nv_bfloat16*)(smc + bo);
    const __nv_bfloat16* Al = (const __nv_bfloat16*)(smc + bo + MATA);
    const __nv_bfloat16* Bh = (const __nv_bfloat16*)(smc + bo + 2 * MATA);
    const __nv_bfloat16* Bl = (const __nv_bfloat16*)(smc + bo + 2 * MATA + MATB1);
#pragma unroll
    for (int k0 = 0; k0 < 32; k0 += 16) {
        AFrag ah[2], al[2];
#pragma unroll
        for (int i = 0; i < 2; i++) {
            wmma::load_matrix_sync(ah[i], Ah + (wm * 32 + i * 16) * LDSA + k0, LDSA);
            wmma::load_matrix_sync(al[i], Al + (wm * 32 + i * 16) * LDSA + k0, LDSA);
        }
#pragma unroll
        for (int jh = 0; jh < 2; jh++) {
            BFragC bh[2], bl[2];
#pragma unroll
            for (int j = 0; j < 2; j++)
                wmma::load_matrix_sync(bh[j], Bh + (wn * 64 + jh * 32 + j * 16) * LDSA + k0, LDSA);
#pragma unroll
            for (int i = 0; i < 2; i++)
#pragma unroll
                for (int j = 0; j < 2; j++)
                    wmma::mma_sync(acc[i][jh * 2 + j], ah[i], bh[j], acc[i][jh * 2 + j]);
#pragma unroll
            for (int j = 0; j < 2; j++)
                wmma::load_matrix_sync(bl[j], Bl + (wn * 64 + jh * 32 + j * 16) * LDSA + k0, LDSA);
#pragma unroll
            for (int i = 0; i < 2; i++)
#pragma unroll
                for (int j = 0; j < 2; j++)
                    wmma::mma_sync(acc[i][jh * 2 + j], ah[i], bl[j], acc[i][jh * 2 + j]);
#pragma unroll
            for (int i = 0; i < 2; i++)
#pragma unroll
                for (int j = 0; j < 2; j++)
                    wmma::mma_sync(acc[i][jh * 2 + j], al[i], bh[j], acc[i][jh * 2 + j]);
        }
    }
}

// one K=32 chunk, gemm2 flavor (B row-major [k][n]); warp tile 32x64, warps 2x4
__device__ __forceinline__ void chunk_g2(const char* smc, int bo, int wm, int wn,
                                         AccFrag acc[2][4]) {
    const __nv_bfloat16* Ah = (const __nv_bfloat16*)(smc + bo);
    const __nv_bfloat16* Al = (const __nv_bfloat16*)(smc + bo + MATA);
    const __nv_bfloat16* Bh = (const __nv_bfloat16*)(smc + bo + 2 * MATA);
    const __nv_bfloat16* Bl = (const __nv_bfloat16*)(smc + bo + 2 * MATA + MATB2);
#pragma unroll
    for (int k0 = 0; k0 < 32; k0 += 16) {
        AFrag ah[2], al[2];
#pragma unroll
        for (int i = 0; i < 2; i++) {
            wmma::load_matrix_sync(ah[i], Ah + (wm * 32 + i * 16) * LDSA + k0, LDSA);
            wmma::load_matrix_sync(al[i], Al + (wm * 32 + i * 16) * LDSA + k0, LDSA);
        }
#pragma unroll
        for (int jh = 0; jh < 2; jh++) {
            BFragR bh[2], bl[2];
#pragma unroll
            for (int j = 0; j < 2; j++)
                wmma::load_matrix_sync(bh[j], Bh + k0 * LDSB2 + wn * 64 + jh * 32 + j * 16, LDSB2);
#pragma unroll
            for (int i = 0; i < 2; i++)
#pragma unroll
                for (int j = 0; j < 2; j++)
                    wmma::mma_sync(acc[i][jh * 2 + j], ah[i], bh[j], acc[i][jh * 2 + j]);
#pragma unroll
            for (int j = 0; j < 2; j++)
                wmma::load_matrix_sync(bl[j], Bl + k0 * LDSB2 + wn * 64 + jh * 32 + j * 16, LDSB2);
#pragma unroll
            for (int i = 0; i < 2; i++)
#pragma unroll
                for (int j = 0; j < 2; j++)
                    wmma::mma_sync(acc[i][jh * 2 + j], ah[i], bl[j], acc[i][jh * 2 + j]);
#pragma unroll
            for (int i = 0; i < 2; i++)
#pragma unroll
                for (int j = 0; j < 2; j++)
                    wmma::mma_sync(acc[i][jh * 2 + j], al[i], bh[j], acc[i][jh * 2 + j]);
        }
    }
}

// ---------------------------------------------------------------------------
// K1: split(ctx*w3)->Ahi/Alo + a=ctx.w1 ; split(q)->Bhi/Blo + c=q.w2
// ---------------------------------------------------------------------------
__global__ void convert_kernel(const float* __restrict__ ctx,
                               const float* __restrict__ qry,
                               const float* __restrict__ w) {
    int gw = (blockIdx.x * blockDim.x + threadIdx.x) >> 5;
    int lane = threadIdx.x & 31;
    if (gw < BB * TT) {
        const float* row = ctx + (size_t)gw * DD;
        float acc = 0.f;
#pragma unroll
        for (int i = 0; i < 4; i++) {
            int col = i * 128 + lane * 4;
            float4 x = *(const float4*)(row + col);
            float4 w1v = *(const float4*)(w + col);
            acc += x.x * w1v.x + x.y * w1v.y + x.z * w1v.z + x.w * w1v.w;
            float4 w3v = *(const float4*)(w + 2 * DD + col);
            uint2 hi, lo;
            split4(x.x * w3v.x, x.y * w3v.y, x.z * w3v.z, x.w * w3v.w, hi, lo);
            size_t o = (size_t)gw * DD + col;
            *(uint2*)((char*)g_Ahi + o * 2) = hi;
            *(uint2*)((char*)g_Alo + o * 2) = lo;
        }
#pragma unroll
        for (int o = 16; o; o >>= 1) acc += __shfl_xor_sync(~0u, acc, o);
        if (lane == 0) g_a[gw] = acc;
    } else {
        int r = gw - BB * TT;
        if (r >= BB * JJ) return;
        const float* row = qry + (size_t)r * DD;
        float acc = 0.f;
#pragma unroll
        for (int i = 0; i < 4; i++) {
            int col = i * 128 + lane * 4;
            float4 x = *(const float4*)(row + col);
            float4 w2v = *(const float4*)(w + DD + col);
            acc += x.x * w2v.x + x.y * w2v.y + x.z * w2v.z + x.w * w2v.w;
            uint2 hi, lo;
            split4(x.x, x.y, x.z, x.w, hi, lo);
            size_t o = (size_t)r * DD + col;
            *(uint2*)((char*)g_Bhi + o * 2) = hi;
            *(uint2*)((char*)g_Blo + o * 2) = lo;
        }
#pragma unroll
        for (int o = 16; o; o >>= 1) acc += __shfl_xor_sync(~0u, acc, o);
        if (lane == 0) g_c[r] = acc;
    }
}

// ---------------------------------------------------------------------------
// K2: GEMM1 (WMMA, 256 thr, 2 CTA/SM): S[b, m0:+64, 0:256] (full J per CTA)
//     fused rowmax + fused column softmax partials (16 per b)
// ---------------------------------------------------------------------------
__global__ __launch_bounds__(256, 2) void gemm1_wmma() {
    extern __shared__ __align__(16) char smc[];
    int tid = threadIdx.x;
    int wid = tid >> 5, wm = wid >> 2, wn = wid & 3;
    int lane = tid & 31;
    int b = blockIdx.y, mt = blockIdx.x, m0 = mt * 64;

    float* a_s = (float*)(smc + G1_AS);
    float* c_s = (float*)(smc + G1_CS);
    if (tid < 64) a_s[tid] = g_a[b * TT + m0 + tid];
    c_s[tid] = g_c[b * JJ + tid];

    const __nv_bfloat16* Ah = g_Ahi + (size_t)(b * TT + m0) * DD;
    const __nv_bfloat16* Al = g_Alo + (size_t)(b * TT + m0) * DD;
    const __nv_bfloat16* Bh = g_Bhi + (size_t)b * JJ * DD;
    const __nv_bfloat16* Bl = g_Blo + (size_t)b * JJ * DD;
    uint32_t sm0 = smem_u32(smc);

    AccFrag acc[2][4];
#pragma unroll
    for (int i = 0; i < 2; i++)
#pragma unroll
        for (int j = 0; j < 4; j++) wmma::fill_fragment(acc[i][j], 0.f);

    auto load_stage = [&](int stg, int kc) {
#pragma unroll 1
        for (int i = tid; i < 512; i += 256) {
            int which = i >> 8, idx = i & 255;
            int row = idx >> 2, seg = idx & 3;
            const __nv_bfloat16* src = (which ? Al : Ah) + (size_t)row * DD + kc + seg * 8;
            cpa16(sm0 + stg + which * MATA + row * 80 + seg * 16, src);
        }
#pragma unroll 1
        for (int i = tid; i < 2048; i += 256) {
            int which = i >> 10, idx = i & 1023;
            int row = idx >> 2, seg = idx & 3;
            const __nv_bfloat16* src = (which ? Bl : Bh) + (size_t)row * DD + kc + seg * 8;
            cpa16(sm0 + stg + 2 * MATA + which * MATB1 + row * 80 + seg * 16, src);
        }
        cpa_commit();
    };

    load_stage(0, 0);
    for (int c = 0; c < 16; c++) {
        int cb = (c & 1) * STG1;
        if (c + 1 < 16) {
            load_stage(((c + 1) & 1) * STG1, (c + 1) * 32);
            cpa_wait<1>();
        } else {
            cpa_wait<0>();
        }
        __syncthreads();
        chunk_g1(smc, cb, wm, wn, acc);
        __syncthreads();
    }

    // epilogue: stage 64x256 to smem (ld 260), bias, coalesced write + rowmax
    float* Su = (float*)smc;
#pragma unroll
    for (int i = 0; i < 2; i++)
#pragma unroll
        for (int j = 0; j < 4; j++)
            wmma::store_matrix_sync(Su + (wm * 32 + i * 16) * 260 + wn * 64 + j * 16,
                                    acc[i][j], 260, wmma::mem_row_major);
    __syncthreads();
    float* Sg = g_S + (size_t)(b * TT + m0) * JJ;
    int c4a = lane * 4, c4b = 128 + lane * 4;
#pragma unroll 1
    for (int r0 = 0; r0 < 64; r0 += 8) {
        int row = r0 + wid;
        float av = a_s[row];
        float4 v1 = *(float4*)&Su[row * 260 + c4a];
        float4 cv1 = *(float4*)&c_s[c4a];
        v1.x += av + cv1.x; v1.y += av + cv1.y; v1.z += av + cv1.z; v1.w += av + cv1.w;
        float4 v2 = *(float4*)&Su[row * 260 + c4b];
        float4 cv2 = *(float4*)&c_s[c4b];
        v2.x += av + cv2.x; v2.y += av + cv2.y; v2.z += av + cv2.z; v2.w += av + cv2.w;
        *(float4*)(Sg + (size_t)row * JJ + c4a) = v1;
        *(float4*)(Sg + (size_t)row * JJ + c4b) = v2;
        float rm = fmaxf(fmaxf(fmaxf(v1.x, v1.y), fmaxf(v1.z, v1.w)),
                         fmaxf(fmaxf(v2.x, v2.y), fmaxf(v2.z, v2.w)));
#pragma unroll
        for (int o = 16; o; o >>= 1) rm = fmaxf(rm, __shfl_xor_sync(~0u, rm, o));
        if (lane == 0) g_rm[b * TT + m0 + row] = rm;
    }

    // fused column softmax partials: each thread owns one column over 64 rows
    int col = tid;
    float m = -3.0e38f, s = 0.f;
    float cval = c_s[col];
#pragma unroll 1
    for (int r = 0; r < 64; r++) {
        float v = Su[r * 260 + col] + a_s[r] + cval;
        if (v > m) { s = s * __expf(m - v) + 1.f; m = v; }
        else s += __expf(v - m);
    }
    g_pm[(b * 16 + mt) * JJ + col] = m;
    g_ps[(b * 16 + mt) * JJ + col] = s;
}

// ---------------------------------------------------------------------------
// K3: b_t = softmax_t(rowmax); h[b,d] = sum_t b_t * ctx
// ---------------------------------------------------------------------------
__global__ __launch_bounds__(128) void bth_kernel(const float* __restrict__ ctx) {
    int b = blockIdx.y, q = blockIdx.x, tid = threadIdx.x;
    int wid = tid >> 5, lane = tid & 31;
    __shared__ float e_s[TT];
    __shared__ float red_m[4], red_s[4];
    float v[8];
    float m = -3.0e38f;
#pragma unroll
    for (int i = 0; i < 8; i++) {
        v[i] = g_rm[b * TT + tid + i * 128];
        m = fmaxf(m, v[i]);
    }
#pragma unroll
    for (int o = 16; o; o >>= 1) m = fmaxf(m, __shfl_xor_sync(~0u, m, o));
    if (lane == 0) red_m[wid] = m;
    __syncthreads();
    m = fmaxf(fmaxf(red_m[0], red_m[1]), fmaxf(red_m[2], red_m[3]));
    float s = 0.f;
#pragma unroll
    for (int i = 0; i < 8; i++) {
        float e = __expf(v[i] - m);
        e_s[tid + i * 128] = e;
        s += e;
    }
#pragma unroll
    for (int o = 16; o; o >>= 1) s += __shfl_xor_sync(~0u, s, o);
    if (lane == 0) red_s[wid] = s;
    __syncthreads();
    float inv = 1.f / (red_s[0] + red_s[1] + red_s[2] + red_s[3]);
    int d = q * 128 + tid;
    const float* cb = ctx + (size_t)b * TT * DD + d;
    float a0 = 0.f, a1 = 0.f, a2 = 0.f, a3 = 0.f;
    for (int t = 0; t < TT; t += 4) {
        a0 += e_s[t + 0] * cb[(size_t)(t + 0) * DD];
        a1 += e_s[t + 1] * cb[(size_t)(t + 1) * DD];
        a2 += e_s[t + 2] * cb[(size_t)(t + 2) * DD];
        a3 += e_s[t + 3] * cb[(size_t)(t + 3) * DD];
    }
    g_h[b * DD + d] = (a0 + a1 + a2 + a3) * inv;
}

// ---------------------------------------------------------------------------
// K4: GEMM2 (WMMA, 256 thr, 2 CTA/SM): U tile 64x256 = softmax_col(S) @ q
//     colstats combine in prologue; fused G epilogue
// ---------------------------------------------------------------------------
__global__ __launch_bounds__(256, 2) void gemm2_wmma(const float* __restrict__ ctx,
                                                     float* __restrict__ out) {
    extern __shared__ __align__(16) char smc[];
    int tid = threadIdx.x;
    int wid = tid >> 5, wm = wid >> 2, wn = wid & 3;
    int lane = tid & 31;
    int b = blockIdx.z, m0 = blockIdx.y * 64, n0 = blockIdx.x * 256;

    float* cm_s = (float*)(smc + G2_CM);
    float* ci_s = (float*)(smc + G2_CI);
    float* h_s = (float*)(smc + G2_HS);
    {
        float M = -3.0e38f;
#pragma unroll
        for (int p = 0; p < 16; p++) M = fmaxf(M, g_pm[(b * 16 + p) * JJ + tid]);
        float S = 0.f;
#pragma unroll
        for (int p = 0; p < 16; p++)
            S += g_ps[(b * 16 + p) * JJ + tid] * __expf(g_pm[(b * 16 + p) * JJ + tid] - M);
        cm_s[tid] = M;
        ci_s[tid] = 1.f / S;
        h_s[tid] = g_h[b * DD + n0 + tid];
    }
    __syncthreads();

    const float* Sg = g_S + (size_t)(b * TT + m0) * JJ;
    const __nv_bfloat16* Bh = g_Bhi + (size_t)b * JJ * DD + n0;
    const __nv_bfloat16* Bl = g_Blo + (size_t)b * JJ * DD + n0;
    uint32_t sm0 = smem_u32(smc);

    AccFrag acc[2][4];
#pragma unroll
    for (int i = 0; i < 2; i++)
#pragma unroll
        for (int j = 0; j < 4; j++) wmma::fill_fragment(acc[i][j], 0.f);

    auto load_stage = [&](int stg, int kc) {
#pragma unroll 1
        for (int i = tid; i < 2048; i += 256) {
            int which = i >> 10, idx = i & 1023;
            int row = idx >> 5, seg = idx & 31;
            const __nv_bfloat16* src =
                (which ? Bl : Bh) + (size_t)(kc + row) * DD + seg * 8;
            cpa16(sm0 + stg + 2 * MATA + which * MATB2 + row * 528 + seg * 16, src);
        }
        cpa_commit();
#pragma unroll 1
        for (int i = tid; i < 512; i += 256) {
            int row = i >> 3, c4 = (i & 7) * 4;
            int jb = kc + c4;
            float4 v = *(const float4*)(Sg + (size_t)row * JJ + jb);
            float p0 = __expf(v.x - cm_s[jb + 0]) * ci_s[jb + 0];
            float p1 = __expf(v.y - cm_s[jb + 1]) * ci_s[jb + 1];
            float p2 = __expf(v.z - cm_s[jb + 2]) * ci_s[jb + 2];
            float p3 = __expf(v.w - cm_s[jb + 3]) * ci_s[jb + 3];
            uint2 hi, lo;
            split4(p0, p1, p2, p3, hi, lo);
            *(uint2*)(smc + stg + row * 80 + c4 * 2) = hi;
            *(uint2*)(smc + stg + MATA + row * 80 + c4 * 2) = lo;
        }
    };

    load_stage(0, 0);
    for (int c = 0; c < 8; c++) {
        int cb = (c & 1) * STG2;
        if (c + 1 < 8) {
            load_stage(((c + 1) & 1) * STG2, (c + 1) * 32);
            cpa_wait<1>();
        } else {
            cpa_wait<0>();
        }
        __syncthreads();
        chunk_g2(smc, cb, wm, wn, acc);
        __syncthreads();
    }

    // epilogue: stage U (64x256, ld 260), fused G = [ctx, U, ctx*U, ctx*h]
    float* Su = (float*)smc;
#pragma unroll
    for (int i = 0; i < 2; i++)
#pragma unroll
        for (int j = 0; j < 4; j++)
            wmma::store_matrix_sync(Su + (wm * 32 + i * 16) * 260 + wn * 64 + j * 16,
                                    acc[i][j], 260, wmma::mem_row_major);
    __syncthreads();
    int c4a = lane * 4, c4b = 128 + lane * 4;
#pragma unroll 1
    for (int r0 = 0; r0 < 64; r0 += 8) {
        int row = r0 + wid;
        const float* crow = ctx + (size_t)(b * TT + m0 + row) * DD + n0;
        float* og = out + (size_t)(b * TT + m0 + row) * 2048 + n0;
#pragma unroll
        for (int half = 0; half < 2; half++) {
            int c4 = half ? c4b : c4a;
            float4 u = *(float4*)&Su[row * 260 + c4];
            float4 cx = *(const float4*)(crow + c4);
            float4 h4 = *(float4*)&h_s[c4];
            float4 cu, ch;
            cu.x = cx.x * u.x; cu.y = cx.y * u.y; cu.z = cx.z * u.z; cu.w = cx.w * u.w;
            ch.x = cx.x * h4.x; ch.y = cx.y * h4.y; ch.z = cx.z * h4.z; ch.w = cx.w * h4.w;
            *(float4*)(og + c4) = cx;
            *(float4*)(og + 512 + c4) = u;
            *(float4*)(og + 1024 + c4) = cu;
            *(float4*)(og + 1536 + c4) = ch;
        }
    }
}

// ---------------------------------------------------------------------------
extern "C" void kernel_launch(void* const* d_in, const int* in_sizes, int n_in,
                              void* d_out, int out_size) {
    const float* ctx = (const float*)d_in[0];
    const float* qry = (const float*)d_in[1];
    const float* w = (const float*)d_in[2];
    float* out = (float*)d_out;

    cudaFuncSetAttribute(gemm1_wmma, cudaFuncAttributeMaxDynamicSharedMemorySize, SMB1);
    cudaFuncSetAttribute(gemm2_wmma, cudaFuncAttributeMaxDynamicSharedMemorySize, SMB2);

    convert_kernel<<<(BB * TT + BB * JJ) / 8, 256>>>(ctx, qry, w);
    gemm1_wmma<<<dim3(TT / 64, BB), 256, SMB1>>>();
    bth_kernel<<<dim3(4, BB), 128>>>(ctx);
    gemm2_wmma<<<dim3(DD / 256, TT / 64, BB), 256, SMB2>>>(ctx, out);
}